// round 3
// baseline (speedup 1.0000x reference)
#include <cuda_runtime.h>
#include <math.h>

// Problem constants (match reference)
#define NN 100000
#define EE 1600000
#define FD 128
#define HD 128
#define OD 256
#define GG 256

// ---------------- scratch (static __device__, no allocs) ----------------
__device__ float g_t[(size_t)NN * HD];     // transformed features (GEMM out)
__device__ float g_h[(size_t)NN * HD];     // layer output features
__device__ int   g_row[EE];
__device__ int   g_col[EE];
__device__ int   g_src[EE];                // CSR: source node per slot
__device__ float g_wgt[EE];                // CSR: edge weight (norm) per slot
__device__ int   g_cnt[NN];                // in-degree (edges only)
__device__ int   g_indptr[NN];             // exclusive prefix of g_cnt
__device__ int   g_cursor[NN];
__device__ int   g_scan[NN];               // per-element exclusive within block
__device__ int   g_bsum[256];              // block sums for scan
__device__ float g_dinv[NN];
__device__ float g_pool[GG * HD];

// ---------------- prep ----------------
__global__ void k_init(int n) {
    int i = blockIdx.x * blockDim.x + threadIdx.x;
    if (i < n) { g_cnt[i] = 0; g_cursor[i] = 0; }
}

// edge_index is int32 (JAX x64 disabled -> int64 request silently becomes int32)
__global__ void k_edges(const int* __restrict__ ei, int e_total, int n) {
    int e = blockIdx.x * blockDim.x + threadIdx.x;
    if (e >= e_total) return;
    int r = ei[e];
    int c = ei[e_total + e];
    if ((unsigned)r >= (unsigned)n || (unsigned)c >= (unsigned)n) { g_row[e] = -1; g_col[e] = -1; return; }
    g_row[e] = r;
    g_col[e] = c;
    atomicAdd(&g_cnt[c], 1);
}

__global__ void k_dinv(int n) {
    int v = blockIdx.x * blockDim.x + threadIdx.x;
    if (v < n) g_dinv[v] = rsqrtf((float)(g_cnt[v] + 1));  // +1 self-loop
}

#define SCAN_B 1024
__global__ void k_scan1(int n) {
    __shared__ int s[SCAN_B];
    int tid = threadIdx.x;
    int v = blockIdx.x * SCAN_B + tid;
    int c = (v < n) ? g_cnt[v] : 0;
    s[tid] = c;
    __syncthreads();
    #pragma unroll
    for (int off = 1; off < SCAN_B; off <<= 1) {
        int t = (tid >= off) ? s[tid - off] : 0;
        __syncthreads();
        s[tid] += t;
        __syncthreads();
    }
    if (v < n) g_scan[v] = s[tid] - c;   // exclusive within block
    if (tid == SCAN_B - 1) g_bsum[blockIdx.x] = s[tid];
}

__global__ void k_scan2(int nblocks) {
    if (threadIdx.x == 0 && blockIdx.x == 0) {
        int acc = 0;
        for (int b = 0; b < nblocks; b++) { int t = g_bsum[b]; g_bsum[b] = acc; acc += t; }
    }
}

__global__ void k_scan3(int n) {
    int v = blockIdx.x * blockDim.x + threadIdx.x;
    if (v < n) g_indptr[v] = g_scan[v] + g_bsum[v >> 10];
}

__global__ void k_fill(int e_total) {
    int e = blockIdx.x * blockDim.x + threadIdx.x;
    if (e >= e_total) return;
    int r = g_row[e];
    int c = g_col[e];
    if (r < 0 || c < 0) return;
    int slot = g_indptr[c] + atomicAdd(&g_cursor[c], 1);
    g_src[slot] = r;
    g_wgt[slot] = g_dinv[r] * g_dinv[c];
}

// ---------------- dense transform: T = X @ W  (X: [n,128], W: [128,128]) ----------------
#define TM 64
#define TK 32
__global__ __launch_bounds__(256) void k_gemm(const float* __restrict__ X,
                                              const float* __restrict__ W,
                                              float* __restrict__ T, int n) {
    __shared__ float Xs[TM][TK + 4];    // row-major, padded
    __shared__ float Ws[TK][128];
    int tid = threadIdx.x;
    int cid = tid & 31;        // col group: cols cid*4..+3
    int rid = tid >> 5;        // row group: rows rid*8..+7
    int row0 = blockIdx.x * TM;

    float acc[8][4];
    #pragma unroll
    for (int i = 0; i < 8; i++)
        #pragma unroll
        for (int j = 0; j < 4; j++) acc[i][j] = 0.0f;

    #pragma unroll 1
    for (int k0 = 0; k0 < 128; k0 += TK) {
        // load X tile: 64 rows x 32 cols = 512 float4, 2 per thread
        #pragma unroll
        for (int i = 0; i < 2; i++) {
            int idx = tid + i * 256;
            int r = idx >> 3;
            int kc = (idx & 7) << 2;
            float4 v = make_float4(0.f, 0.f, 0.f, 0.f);
            int gr = row0 + r;
            if (gr < n) v = *(const float4*)(X + (size_t)gr * 128 + k0 + kc);
            *(float4*)&Xs[r][kc] = v;
        }
        // load W tile: 32 rows x 128 cols = 1024 float4, 4 per thread
        #pragma unroll
        for (int i = 0; i < 4; i++) {
            int idx = tid + i * 256;
            int kr = idx >> 5;
            int c = (idx & 31) << 2;
            *(float4*)&Ws[kr][c] = *(const float4*)(W + (size_t)(k0 + kr) * 128 + c);
        }
        __syncthreads();
        #pragma unroll 8
        for (int k = 0; k < TK; k++) {
            float4 b = *(const float4*)&Ws[k][cid << 2];
            #pragma unroll
            for (int i = 0; i < 8; i++) {
                float a = Xs[(rid << 3) + i][k];
                acc[i][0] += a * b.x;
                acc[i][1] += a * b.y;
                acc[i][2] += a * b.z;
                acc[i][3] += a * b.w;
            }
        }
        __syncthreads();
    }
    #pragma unroll
    for (int i = 0; i < 8; i++) {
        int gr = row0 + (rid << 3) + i;
        if (gr < n) {
            float4 v = make_float4(acc[i][0], acc[i][1], acc[i][2], acc[i][3]);
            *(float4*)(T + (size_t)gr * 128 + (cid << 2)) = v;
        }
    }
}

// ---------------- aggregate: H[v] = relu( dinv[v]^2*T[v] + sum_e w*T[src] + bias ) ----------------
__global__ __launch_bounds__(256) void k_agg(const float* __restrict__ T,
                                             const float* __restrict__ bias,
                                             float* __restrict__ H, int n) {
    int warp = (blockIdx.x * blockDim.x + threadIdx.x) >> 5;
    int lane = threadIdx.x & 31;
    if (warp >= n) return;
    int v = warp;
    const float4* T4 = (const float4*)T;
    float dv = g_dinv[v];
    float4 acc = T4[(size_t)v * 32 + lane];
    float s = dv * dv;
    acc.x *= s; acc.y *= s; acc.z *= s; acc.w *= s;

    int start = g_indptr[v];
    int cnt = g_cursor[v];   // number actually filled (equals g_cnt for valid edges)
    int i = 0;
    for (; i + 2 <= cnt; i += 2) {
        int s0 = g_src[start + i];
        int s1 = g_src[start + i + 1];
        float w0 = g_wgt[start + i];
        float w1 = g_wgt[start + i + 1];
        float4 x0 = T4[(size_t)s0 * 32 + lane];
        float4 x1 = T4[(size_t)s1 * 32 + lane];
        acc.x += w0 * x0.x + w1 * x1.x;
        acc.y += w0 * x0.y + w1 * x1.y;
        acc.z += w0 * x0.z + w1 * x1.z;
        acc.w += w0 * x0.w + w1 * x1.w;
    }
    if (i < cnt) {
        int s0 = g_src[start + i];
        float w0 = g_wgt[start + i];
        float4 x0 = T4[(size_t)s0 * 32 + lane];
        acc.x += w0 * x0.x; acc.y += w0 * x0.y; acc.z += w0 * x0.z; acc.w += w0 * x0.w;
    }
    float4 b = ((const float4*)bias)[lane];
    acc.x = fmaxf(acc.x + b.x, 0.f);
    acc.y = fmaxf(acc.y + b.y, 0.f);
    acc.z = fmaxf(acc.z + b.z, 0.f);
    acc.w = fmaxf(acc.w + b.w, 0.f);
    ((float4*)H)[(size_t)v * 32 + lane] = acc;
}

// ---------------- pool: per-graph mean over sorted batch ids (int32) ----------------
__device__ __forceinline__ int lb_i(const int* a, int n, int key) {
    int lo = 0, hi = n;
    while (lo < hi) { int mid = (lo + hi) >> 1; if (a[mid] < key) lo = mid + 1; else hi = mid; }
    return lo;
}

__global__ void k_pool(const float* __restrict__ H, const int* __restrict__ batch, int n) {
    int g = blockIdx.x;               // 0..GG-1
    __shared__ int s_lo, s_hi;
    if (threadIdx.x == 0) s_lo = lb_i(batch, n, g);
    if (threadIdx.x == 1) s_hi = lb_i(batch, n, g + 1);
    __syncthreads();
    int lo = s_lo, hi = s_hi;
    int k = threadIdx.x;              // feature 0..127
    float acc = 0.f;
    for (int v = lo; v < hi; v++) acc += H[(size_t)v * 128 + k];
    float cntf = (float)(hi - lo);
    g_pool[g * 128 + k] = acc / fmaxf(cntf, 1.0f);
}

// ---------------- fc: out = pooled @ Wfc + bfc ----------------
__global__ void k_fc(const float* __restrict__ Wfc, const float* __restrict__ bfc,
                     float* __restrict__ out) {
    int g = blockIdx.x;
    int o = threadIdx.x;              // 0..255
    __shared__ float p[128];
    if (threadIdx.x < 128) p[threadIdx.x] = g_pool[g * 128 + threadIdx.x];
    __syncthreads();
    float acc = bfc[o];
    #pragma unroll 8
    for (int k = 0; k < 128; k++) acc += p[k] * Wfc[(size_t)k * 256 + o];
    out[(size_t)g * 256 + o] = acc;
}

// ---------------- launch ----------------
extern "C" void kernel_launch(void* const* d_in, const int* in_sizes, int n_in,
                              void* d_out, int out_size) {
    // Size-based binding (robust to metadata ordering).
    const float *x = 0, *Wfc = 0, *bfc = 0;
    const float *Wl[3] = {0, 0, 0};
    const float *bl[3] = {0, 0, 0};
    const int *ei = 0, *batch = 0;
    int nW = 0, nb = 0;
    for (int i = 0; i < n_in; i++) {
        int s = in_sizes[i];
        const void* p = d_in[i];
        if (s == NN * FD)            x = (const float*)p;          // 12,800,000
        else if (s == FD * HD) {     if (nW < 3) Wl[nW++] = (const float*)p; }  // 16384 x3
        else if (s == HD)        {   if (nb < 3) bl[nb++] = (const float*)p; }  // 128 x3
        else if (s == HD * OD)       Wfc = (const float*)p;        // 32768
        else if (s == OD)            bfc = (const float*)p;        // 256
        else if (s == 2 * EE)        ei = (const int*)p;           // 3,200,000 (int32)
        else if (s == NN)            batch = (const int*)p;        // 100,000 (int32)
    }
    float* out = (float*)d_out;

    int n = NN;
    int e = EE;

    float *t_ptr, *h_ptr;
    cudaGetSymbolAddress((void**)&t_ptr, g_t);
    cudaGetSymbolAddress((void**)&h_ptr, g_h);

    int nb_n = (n + 255) / 256;
    int nb_e = (e + 255) / 256;
    int nb_scan = (n + SCAN_B - 1) / SCAN_B;
    int nb_gemm = (n + TM - 1) / TM;
    int nb_agg = (n * 32 + 255) / 256;

    // prep: degree + CSR by target
    k_init<<<nb_n, 256>>>(n);
    k_edges<<<nb_e, 256>>>(ei, e, n);
    k_dinv<<<nb_n, 256>>>(n);
    k_scan1<<<nb_scan, SCAN_B>>>(n);
    k_scan2<<<1, 32>>>(nb_scan);
    k_scan3<<<nb_n, 256>>>(n);
    k_fill<<<nb_e, 256>>>(e);

    // layer 1
    k_gemm<<<nb_gemm, 256>>>(x, Wl[0], t_ptr, n);
    k_agg<<<nb_agg, 256>>>(t_ptr, bl[0], h_ptr, n);
    // layer 2
    k_gemm<<<nb_gemm, 256>>>(h_ptr, Wl[1], t_ptr, n);
    k_agg<<<nb_agg, 256>>>(t_ptr, bl[1], h_ptr, n);
    // layer 3
    k_gemm<<<nb_gemm, 256>>>(h_ptr, Wl[2], t_ptr, n);
    k_agg<<<nb_agg, 256>>>(t_ptr, bl[2], h_ptr, n);

    // pool + fc
    k_pool<<<GG, 128>>>(h_ptr, batch, n);
    k_fc<<<GG, 256>>>(Wfc, bfc, out);
}

// round 8
// speedup vs baseline: 1.0045x; 1.0045x over previous
#include <cuda_runtime.h>
#include <cuda_bf16.h>
#include <math.h>
#include <stdint.h>

// Problem constants
#define NN 100000
#define EE 1600000
#define FD 128
#define HD 128
#define OD 256
#define GG 256
#define NT 782              // ceil(NN/128) row tiles; NT*128 = 100096 rows

// ---------------- scratch ----------------
__device__ float g_t[(size_t)NN * HD];
__device__ float g_h[(size_t)NN * HD];
__device__ __nv_bfloat16 g_ah[(size_t)NT * 128 * 128];  // A hi, plain [row*128+k]
__device__ __nv_bfloat16 g_al[(size_t)NT * 128 * 128];  // A lo
__device__ __nv_bfloat16 g_bh[3 * 128 * 128];           // W^T hi per layer [n*128+k]
__device__ __nv_bfloat16 g_bl[3 * 128 * 128];           // W^T lo
__device__ int   g_rowe[EE];
__device__ int   g_cole[EE];
__device__ int   g_src[EE];
__device__ float g_wgt[EE];
__device__ int   g_cnt[NN];
__device__ int   g_indptr[NN];
__device__ int   g_cursor[NN];
__device__ int   g_scan[NN];
__device__ int   g_bsum[256];
__device__ float g_dinv[NN];
__device__ float g_pool[GG * HD];

// ---------------- helpers ----------------
__device__ __forceinline__ unsigned long long pack_hi4(float4 v, float4* lo_out) {
    __nv_bfloat16 h0 = __float2bfloat16(v.x), h1 = __float2bfloat16(v.y);
    __nv_bfloat16 h2 = __float2bfloat16(v.z), h3 = __float2bfloat16(v.w);
    lo_out->x = v.x - __bfloat162float(h0);
    lo_out->y = v.y - __bfloat162float(h1);
    lo_out->z = v.z - __bfloat162float(h2);
    lo_out->w = v.w - __bfloat162float(h3);
    return (unsigned long long)__bfloat16_as_ushort(h0)
         | ((unsigned long long)__bfloat16_as_ushort(h1) << 16)
         | ((unsigned long long)__bfloat16_as_ushort(h2) << 32)
         | ((unsigned long long)__bfloat16_as_ushort(h3) << 48);
}
__device__ __forceinline__ unsigned long long pack_lo4(float4 v) {
    return (unsigned long long)__bfloat16_as_ushort(__float2bfloat16(v.x))
         | ((unsigned long long)__bfloat16_as_ushort(__float2bfloat16(v.y)) << 16)
         | ((unsigned long long)__bfloat16_as_ushort(__float2bfloat16(v.z)) << 32)
         | ((unsigned long long)__bfloat16_as_ushort(__float2bfloat16(v.w)) << 48);
}

__device__ __forceinline__ void mma_bf16(float* c, uint32_t a0, uint32_t a1,
                                         uint32_t a2, uint32_t a3,
                                         uint32_t b0, uint32_t b1) {
    asm volatile(
        "mma.sync.aligned.m16n8k16.row.col.f32.bf16.bf16.f32 "
        "{%0,%1,%2,%3}, {%4,%5,%6,%7}, {%8,%9}, {%0,%1,%2,%3};"
        : "+f"(c[0]), "+f"(c[1]), "+f"(c[2]), "+f"(c[3])
        : "r"(a0), "r"(a1), "r"(a2), "r"(a3), "r"(b0), "r"(b1));
}

// ---------------- prep ----------------
__global__ void k_init(int n) {
    int i = blockIdx.x * blockDim.x + threadIdx.x;
    if (i < n) { g_cnt[i] = 0; g_cursor[i] = 0; }
}

// edge_index is int32 (JAX x64 disabled)
__global__ void k_edges(const int* __restrict__ ei, int e_total, int n) {
    int e = blockIdx.x * blockDim.x + threadIdx.x;
    if (e >= e_total) return;
    int r = ei[e];
    int c = ei[e_total + e];
    if ((unsigned)r >= (unsigned)n || (unsigned)c >= (unsigned)n) { g_rowe[e] = -1; g_cole[e] = -1; return; }
    g_rowe[e] = r; g_cole[e] = c;
    atomicAdd(&g_cnt[c], 1);
}

__global__ void k_dinv(int n) {
    int v = blockIdx.x * blockDim.x + threadIdx.x;
    if (v < n) g_dinv[v] = rsqrtf((float)(g_cnt[v] + 1));
}

#define SCAN_B 1024
__global__ void k_scan1(int n) {
    __shared__ int s[SCAN_B];
    int tid = threadIdx.x;
    int v = blockIdx.x * SCAN_B + tid;
    int c = (v < n) ? g_cnt[v] : 0;
    s[tid] = c;
    __syncthreads();
    #pragma unroll
    for (int off = 1; off < SCAN_B; off <<= 1) {
        int t = (tid >= off) ? s[tid - off] : 0;
        __syncthreads();
        s[tid] += t;
        __syncthreads();
    }
    if (v < n) g_scan[v] = s[tid] - c;
    if (tid == SCAN_B - 1) g_bsum[blockIdx.x] = s[tid];
}

__global__ void k_scan2(int nblocks) {
    if (threadIdx.x == 0 && blockIdx.x == 0) {
        int acc = 0;
        for (int b = 0; b < nblocks; b++) { int t = g_bsum[b]; g_bsum[b] = acc; acc += t; }
    }
}

__global__ void k_scan3(int n) {
    int v = blockIdx.x * blockDim.x + threadIdx.x;
    if (v < n) g_indptr[v] = g_scan[v] + g_bsum[v >> 10];
}

__global__ void k_fill(int e_total) {
    int e = blockIdx.x * blockDim.x + threadIdx.x;
    if (e >= e_total) return;
    int r = g_rowe[e], c = g_cole[e];
    if (r < 0 || c < 0) return;
    int slot = g_indptr[c] + atomicAdd(&g_cursor[c], 1);
    g_src[slot] = r;
    g_wgt[slot] = g_dinv[r] * g_dinv[c];
}

// W^T -> bf16 hi/lo, plain [n*128+k]
__global__ void k_prep_w(const float* __restrict__ W, int layer) {
    int nidx = threadIdx.x;   // output col 0..127
    __nv_bfloat16* bh = g_bh + (size_t)layer * 128 * 128;
    __nv_bfloat16* bl = g_bl + (size_t)layer * 128 * 128;
    for (int k = 0; k < 128; k++) {
        float w = W[k * 128 + nidx];
        __nv_bfloat16 hi = __float2bfloat16(w);
        __nv_bfloat16 lo = __float2bfloat16(w - __bfloat162float(hi));
        bh[nidx * 128 + k] = hi;
        bl[nidx * 128 + k] = lo;
    }
}

// x (fp32) -> bf16 hi/lo plain rows
__global__ __launch_bounds__(256) void k_convert_x(const float* __restrict__ X, int n) {
    int warp = (blockIdx.x * blockDim.x + threadIdx.x) >> 5;
    int lane = threadIdx.x & 31;
    if (warp >= n) return;
    float4 v = ((const float4*)X)[(size_t)warp * 32 + lane];
    float4 lo4;
    unsigned long long hp = pack_hi4(v, &lo4);
    unsigned long long lp = pack_lo4(lo4);
    size_t off = (size_t)warp * 128 + lane * 4;
    *(unsigned long long*)(g_ah + off) = hp;
    *(unsigned long long*)(g_al + off) = lp;
}

// ---------------- HMMA GEMM: T = A @ W  (bf16 hi/lo 3-product, fp32 accum) ----------------
// Block: 128 rows x 128 cols, 8 warps each own 16 rows.
#define BPAD 72   // padded K-half row length (elements); 144B rows -> conflict-free
__global__ __launch_bounds__(256) void k_gemm_mma(const __nv_bfloat16* __restrict__ Ah,
                                                  const __nv_bfloat16* __restrict__ Al,
                                                  const __nv_bfloat16* __restrict__ Bh,
                                                  const __nv_bfloat16* __restrict__ Bl,
                                                  float* __restrict__ T, int n) {
    __shared__ __align__(16) __nv_bfloat16 sBh[128][BPAD];
    __shared__ __align__(16) __nv_bfloat16 sBl[128][BPAD];

    int tid = threadIdx.x;
    int wid = tid >> 5;
    int lane = tid & 31;
    int g = lane >> 2;        // 0..7
    int t = lane & 3;         // 0..3
    int row_base = blockIdx.x * 128 + wid * 16;
    int r0 = row_base + g;    // rows r0 and r0+8

    float acc[16][4];
    #pragma unroll
    for (int nt = 0; nt < 16; nt++)
        #pragma unroll
        for (int j = 0; j < 4; j++) acc[nt][j] = 0.0f;

    #pragma unroll 1
    for (int kh = 0; kh < 2; kh++) {
        // stage W^T K-half into smem (hi + lo): 128 rows x 64 elems each
        {
            const uint4* srcH = (const uint4*)(Bh + kh * 64);
            const uint4* srcL = (const uint4*)(Bl + kh * 64);
            // row n, chunk q (8 elems): global uint4 index = n*16 + q (row stride 128 elems = 16 uint4)
            #pragma unroll
            for (int i = tid; i < 128 * 8; i += 256) {
                int nrow = i >> 3, q = i & 7;
                *(uint4*)&sBh[nrow][q * 8] = srcH[nrow * 16 + q];
                *(uint4*)&sBl[nrow][q * 8] = srcL[nrow * 16 + q];
            }
        }
        __syncthreads();

        #pragma unroll
        for (int kc = 0; kc < 4; kc++) {
            int kabs = kh * 64 + kc * 16;
            // A fragments (hi and lo), rows r0 / r0+8, cols kabs + t*2 (+8)
            const __nv_bfloat16* pa0 = Ah + (size_t)r0 * 128 + kabs + t * 2;
            const __nv_bfloat16* pa1 = pa0 + 8 * 128;
            const __nv_bfloat16* pl0 = Al + (size_t)r0 * 128 + kabs + t * 2;
            const __nv_bfloat16* pl1 = pl0 + 8 * 128;
            uint32_t ah0 = *(const uint32_t*)pa0;
            uint32_t ah1 = *(const uint32_t*)pa1;
            uint32_t ah2 = *(const uint32_t*)(pa0 + 8);
            uint32_t ah3 = *(const uint32_t*)(pa1 + 8);
            uint32_t al0 = *(const uint32_t*)pl0;
            uint32_t al1 = *(const uint32_t*)pl1;
            uint32_t al2 = *(const uint32_t*)(pl0 + 8);
            uint32_t al3 = *(const uint32_t*)(pl1 + 8);

            int ks = kc * 16 + t * 2;   // within the 64-wide half
            #pragma unroll
            for (int nt = 0; nt < 16; nt++) {
                int nrow = nt * 8 + g;
                uint32_t bh0 = *(const uint32_t*)&sBh[nrow][ks];
                uint32_t bh1 = *(const uint32_t*)&sBh[nrow][ks + 8];
                uint32_t bl0 = *(const uint32_t*)&sBl[nrow][ks];
                uint32_t bl1 = *(const uint32_t*)&sBl[nrow][ks + 8];
                mma_bf16(acc[nt], ah0, ah1, ah2, ah3, bh0, bh1);
                mma_bf16(acc[nt], ah0, ah1, ah2, ah3, bl0, bl1);
                mma_bf16(acc[nt], al0, al1, al2, al3, bh0, bh1);
            }
        }
        __syncthreads();
    }

    // epilogue: C fragment (row g / g+8, col n0 + t*2, t*2+1)
    bool w0 = (r0 < n), w1 = (r0 + 8 < n);
    #pragma unroll
    for (int nt = 0; nt < 16; nt++) {
        int col = nt * 8 + t * 2;
        if (w0) *(float2*)(T + (size_t)r0 * 128 + col)       = make_float2(acc[nt][0], acc[nt][1]);
        if (w1) *(float2*)(T + (size_t)(r0 + 8) * 128 + col) = make_float2(acc[nt][2], acc[nt][3]);
    }
}

// ---------------- aggregate ----------------
// MODE 0: write bf16 hi/lo (feeds next GEMM); MODE 1: write fp32 H (feeds pool)
template<int MODE>
__global__ __launch_bounds__(256) void k_agg_t(const float* __restrict__ T,
                                               const float* __restrict__ bias,
                                               float* __restrict__ H, int n) {
    int warp = (blockIdx.x * blockDim.x + threadIdx.x) >> 5;
    int lane = threadIdx.x & 31;
    if (warp >= n) return;
    int v = warp;
    const float4* T4 = (const float4*)T;
    float dv = g_dinv[v];
    float4 acc = T4[(size_t)v * 32 + lane];
    float s = dv * dv;
    acc.x *= s; acc.y *= s; acc.z *= s; acc.w *= s;

    int start = g_indptr[v];
    int cnt = g_cursor[v];
    int i = 0;
    for (; i + 4 <= cnt; i += 4) {
        int s0 = g_src[start + i],     s1 = g_src[start + i + 1];
        int s2 = g_src[start + i + 2], s3 = g_src[start + i + 3];
        float w0 = g_wgt[start + i],     w1 = g_wgt[start + i + 1];
        float w2 = g_wgt[start + i + 2], w3 = g_wgt[start + i + 3];
        float4 x0 = T4[(size_t)s0 * 32 + lane];
        float4 x1 = T4[(size_t)s1 * 32 + lane];
        float4 x2 = T4[(size_t)s2 * 32 + lane];
        float4 x3 = T4[(size_t)s3 * 32 + lane];
        acc.x += w0 * x0.x + w1 * x1.x + w2 * x2.x + w3 * x3.x;
        acc.y += w0 * x0.y + w1 * x1.y + w2 * x2.y + w3 * x3.y;
        acc.z += w0 * x0.z + w1 * x1.z + w2 * x2.z + w3 * x3.z;
        acc.w += w0 * x0.w + w1 * x1.w + w2 * x2.w + w3 * x3.w;
    }
    for (; i < cnt; i++) {
        int s0 = g_src[start + i];
        float w0 = g_wgt[start + i];
        float4 x0 = T4[(size_t)s0 * 32 + lane];
        acc.x += w0 * x0.x; acc.y += w0 * x0.y; acc.z += w0 * x0.z; acc.w += w0 * x0.w;
    }
    float4 b = ((const float4*)bias)[lane];
    acc.x = fmaxf(acc.x + b.x, 0.f);
    acc.y = fmaxf(acc.y + b.y, 0.f);
    acc.z = fmaxf(acc.z + b.z, 0.f);
    acc.w = fmaxf(acc.w + b.w, 0.f);

    if (MODE == 1) {
        ((float4*)H)[(size_t)v * 32 + lane] = acc;
    } else {
        float4 lo4;
        unsigned long long hp = pack_hi4(acc, &lo4);
        unsigned long long lp = pack_lo4(lo4);
        size_t off = (size_t)v * 128 + lane * 4;
        *(unsigned long long*)(g_ah + off) = hp;
        *(unsigned long long*)(g_al + off) = lp;
    }
}

// ---------------- pool ----------------
__device__ __forceinline__ int lb_i(const int* a, int n, int key) {
    int lo = 0, hi = n;
    while (lo < hi) { int mid = (lo + hi) >> 1; if (a[mid] < key) lo = mid + 1; else hi = mid; }
    return lo;
}

__global__ void k_pool(const float* __restrict__ H, const int* __restrict__ batch, int n) {
    int g = blockIdx.x;
    __shared__ int s_lo, s_hi;
    if (threadIdx.x == 0) s_lo = lb_i(batch, n, g);
    if (threadIdx.x == 1) s_hi = lb_i(batch, n, g + 1);
    __syncthreads();
    int lo = s_lo, hi = s_hi;
    int k = threadIdx.x;
    float acc = 0.f;
    for (int v = lo; v < hi; v++) acc += H[(size_t)v * 128 + k];
    g_pool[g * 128 + k] = acc / fmaxf((float)(hi - lo), 1.0f);
}

__global__ void k_fc(const float* __restrict__ Wfc, const float* __restrict__ bfc,
                     float* __restrict__ out) {
    int g = blockIdx.x;
    int o = threadIdx.x;
    __shared__ float p[128];
    if (threadIdx.x < 128) p[threadIdx.x] = g_pool[g * 128 + threadIdx.x];
    __syncthreads();
    float acc = bfc[o];
    #pragma unroll 8
    for (int k = 0; k < 128; k++) acc += p[k] * Wfc[(size_t)k * 256 + o];
    out[(size_t)g * 256 + o] = acc;
}

// ---------------- launch ----------------
extern "C" void kernel_launch(void* const* d_in, const int* in_sizes, int n_in,
                              void* d_out, int out_size) {
    const float *x = 0, *Wfc = 0, *bfc = 0;
    const float *Wl[3] = {0, 0, 0};
    const float *bl[3] = {0, 0, 0};
    const int *ei = 0, *batch = 0;
    int nW = 0, nb = 0;
    for (int i = 0; i < n_in; i++) {
        int s = in_sizes[i];
        const void* p = d_in[i];
        if (s == NN * FD)            x = (const float*)p;
        else if (s == FD * HD) {     if (nW < 3) Wl[nW++] = (const float*)p; }
        else if (s == HD)        {   if (nb < 3) bl[nb++] = (const float*)p; }
        else if (s == HD * OD)       Wfc = (const float*)p;
        else if (s == OD)            bfc = (const float*)p;
        else if (s == 2 * EE)        ei = (const int*)p;
        else if (s == NN)            batch = (const int*)p;
    }
    float* out = (float*)d_out;

    int n = NN, e = EE;

    float *t_ptr, *h_ptr;
    cudaGetSymbolAddress((void**)&t_ptr, g_t);
    cudaGetSymbolAddress((void**)&h_ptr, g_h);
    __nv_bfloat16 *ah_ptr, *al_ptr, *bh_ptr, *bl_ptr;
    cudaGetSymbolAddress((void**)&ah_ptr, g_ah);
    cudaGetSymbolAddress((void**)&al_ptr, g_al);
    cudaGetSymbolAddress((void**)&bh_ptr, g_bh);
    cudaGetSymbolAddress((void**)&bl_ptr, g_bl);

    int nb_n = (n + 255) / 256;
    int nb_e = (e + 255) / 256;
    int nb_scan = (n + SCAN_B - 1) / SCAN_B;
    int nb_warp = (n * 32 + 255) / 256;

    // prep: degree + CSR by target
    k_init<<<nb_n, 256>>>(n);
    k_edges<<<nb_e, 256>>>(ei, e, n);
    k_dinv<<<nb_n, 256>>>(n);
    k_scan1<<<nb_scan, SCAN_B>>>(n);
    k_scan2<<<1, 32>>>(nb_scan);
    k_scan3<<<nb_n, 256>>>(n);
    k_fill<<<nb_e, 256>>>(e);

    // weights + input -> bf16 hi/lo
    k_prep_w<<<1, 128>>>(Wl[0], 0);
    k_prep_w<<<1, 128>>>(Wl[1], 1);
    k_prep_w<<<1, 128>>>(Wl[2], 2);
    k_convert_x<<<nb_warp, 256>>>(x, n);

    // layer 1
    k_gemm_mma<<<NT, 256>>>(ah_ptr, al_ptr, bh_ptr, bl_ptr, t_ptr, n);
    k_agg_t<0><<<nb_warp, 256>>>(t_ptr, bl[0], h_ptr, n);
    // layer 2
    k_gemm_mma<<<NT, 256>>>(ah_ptr, al_ptr, bh_ptr + 128 * 128, bl_ptr + 128 * 128, t_ptr, n);
    k_agg_t<0><<<nb_warp, 256>>>(t_ptr, bl[1], h_ptr, n);
    // layer 3
    k_gemm_mma<<<NT, 256>>>(ah_ptr, al_ptr, bh_ptr + 2 * 128 * 128, bl_ptr + 2 * 128 * 128, t_ptr, n);
    k_agg_t<1><<<nb_warp, 256>>>(t_ptr, bl[2], h_ptr, n);

    // pool + fc
    k_pool<<<GG, 128>>>(h_ptr, batch, n);
    k_fc<<<GG, 256>>>(Wfc, bfc, out);
}

// round 9
// speedup vs baseline: 1.2555x; 1.2499x over previous
#include <cuda_runtime.h>
#include <cuda_bf16.h>
#include <math.h>
#include <stdint.h>

// Problem constants
#define NN 100000
#define EE 1600000
#define FD 128
#define HD 128
#define OD 256
#define GG 256
#define NT 782              // ceil(NN/128) row tiles; NT*128 = 100096 rows

// ---------------- scratch ----------------
__device__ float g_t[(size_t)NN * HD];
__device__ float g_h[(size_t)NN * HD];
__device__ __nv_bfloat16 g_ah[(size_t)NT * 128 * 128];  // A hi, plain [row*128+k]
__device__ __nv_bfloat16 g_al[(size_t)NT * 128 * 128];  // A lo
__device__ __nv_bfloat16 g_bh[3 * 128 * 128];           // W^T hi per layer [n*128+k]
__device__ __nv_bfloat16 g_bl[3 * 128 * 128];           // W^T lo
__device__ int   g_rowe[EE];
__device__ int   g_cole[EE];
__device__ int   g_src[EE];
__device__ float g_wgt[EE];
__device__ int   g_cnt[NN];
__device__ int   g_indptr[NN];
__device__ int   g_cursor[NN];
__device__ int   g_scan[NN];
__device__ int   g_bsum[256];
__device__ float g_dinv[NN];
__device__ float g_pool[GG * HD];

// ---------------- helpers ----------------
__device__ __forceinline__ unsigned long long pack_hi4(float4 v, float4* lo_out) {
    __nv_bfloat16 h0 = __float2bfloat16(v.x), h1 = __float2bfloat16(v.y);
    __nv_bfloat16 h2 = __float2bfloat16(v.z), h3 = __float2bfloat16(v.w);
    lo_out->x = v.x - __bfloat162float(h0);
    lo_out->y = v.y - __bfloat162float(h1);
    lo_out->z = v.z - __bfloat162float(h2);
    lo_out->w = v.w - __bfloat162float(h3);
    return (unsigned long long)__bfloat16_as_ushort(h0)
         | ((unsigned long long)__bfloat16_as_ushort(h1) << 16)
         | ((unsigned long long)__bfloat16_as_ushort(h2) << 32)
         | ((unsigned long long)__bfloat16_as_ushort(h3) << 48);
}
__device__ __forceinline__ unsigned long long pack_lo4(float4 v) {
    return (unsigned long long)__bfloat16_as_ushort(__float2bfloat16(v.x))
         | ((unsigned long long)__bfloat16_as_ushort(__float2bfloat16(v.y)) << 16)
         | ((unsigned long long)__bfloat16_as_ushort(__float2bfloat16(v.z)) << 32)
         | ((unsigned long long)__bfloat16_as_ushort(__float2bfloat16(v.w)) << 48);
}

__device__ __forceinline__ void mma_bf16(float* c, uint32_t a0, uint32_t a1,
                                         uint32_t a2, uint32_t a3,
                                         uint32_t b0, uint32_t b1) {
    asm volatile(
        "mma.sync.aligned.m16n8k16.row.col.f32.bf16.bf16.f32 "
        "{%0,%1,%2,%3}, {%4,%5,%6,%7}, {%8,%9}, {%0,%1,%2,%3};"
        : "+f"(c[0]), "+f"(c[1]), "+f"(c[2]), "+f"(c[3])
        : "r"(a0), "r"(a1), "r"(a2), "r"(a3), "r"(b0), "r"(b1));
}

// ---------------- prep ----------------
__global__ void k_init(int n) {
    int i = blockIdx.x * blockDim.x + threadIdx.x;
    if (i < n) { g_cnt[i] = 0; g_cursor[i] = 0; }
}

// edge_index is int32 (JAX x64 disabled)
__global__ void k_edges(const int* __restrict__ ei, int e_total, int n) {
    int e = blockIdx.x * blockDim.x + threadIdx.x;
    if (e >= e_total) return;
    int r = ei[e];
    int c = ei[e_total + e];
    if ((unsigned)r >= (unsigned)n || (unsigned)c >= (unsigned)n) { g_rowe[e] = -1; g_cole[e] = -1; return; }
    g_rowe[e] = r; g_cole[e] = c;
    atomicAdd(&g_cnt[c], 1);
}

#define SCAN_B 1024
// block-level scan + per-node dinv (fused)
__global__ void k_scan1(int n) {
    __shared__ int s[SCAN_B];
    int tid = threadIdx.x;
    int v = blockIdx.x * SCAN_B + tid;
    int c = (v < n) ? g_cnt[v] : 0;
    if (v < n) g_dinv[v] = rsqrtf((float)(c + 1));   // +1 self-loop
    s[tid] = c;
    __syncthreads();
    #pragma unroll
    for (int off = 1; off < SCAN_B; off <<= 1) {
        int t = (tid >= off) ? s[tid - off] : 0;
        __syncthreads();
        s[tid] += t;
        __syncthreads();
    }
    if (v < n) g_scan[v] = s[tid] - c;
    if (tid == SCAN_B - 1) g_bsum[blockIdx.x] = s[tid];
}

// parallel exclusive scan of block sums (nblocks <= 128)
__global__ void k_scan2(int nblocks) {
    __shared__ int s[128];
    int t = threadIdx.x;
    int v = (t < nblocks) ? g_bsum[t] : 0;
    s[t] = v;
    __syncthreads();
    #pragma unroll
    for (int off = 1; off < 128; off <<= 1) {
        int u = (t >= off) ? s[t - off] : 0;
        __syncthreads();
        s[t] += u;
        __syncthreads();
    }
    if (t < nblocks) g_bsum[t] = s[t] - v;   // exclusive
}

__global__ void k_scan3(int n) {
    int v = blockIdx.x * blockDim.x + threadIdx.x;
    if (v < n) g_indptr[v] = g_scan[v] + g_bsum[v >> 10];
}

__global__ void k_fill(int e_total) {
    int e = blockIdx.x * blockDim.x + threadIdx.x;
    if (e >= e_total) return;
    int r = g_rowe[e], c = g_cole[e];
    if (r < 0 || c < 0) return;
    int slot = g_indptr[c] + atomicAdd(&g_cursor[c], 1);
    g_src[slot] = r;
    g_wgt[slot] = g_dinv[r] * g_dinv[c];
}

// W^T -> bf16 hi/lo for all 3 layers, coalesced smem-tile transpose.
// grid (4,4,3), block (32,8). Layer z, k-tile y, n-tile x.
__global__ void k_prep_w_all(const float* __restrict__ W0,
                             const float* __restrict__ W1,
                             const float* __restrict__ W2) {
    __shared__ float tile[32][33];
    int l = blockIdx.z;
    const float* W = (l == 0) ? W0 : ((l == 1) ? W1 : W2);
    int k0 = blockIdx.y * 32;
    int n0 = blockIdx.x * 32;
    int tx = threadIdx.x, ty = threadIdx.y;
    #pragma unroll
    for (int i = 0; i < 32; i += 8)
        tile[ty + i][tx] = W[(size_t)(k0 + ty + i) * 128 + n0 + tx];   // coalesced read
    __syncthreads();
    __nv_bfloat16* bh = g_bh + (size_t)l * 16384;
    __nv_bfloat16* bl = g_bl + (size_t)l * 16384;
    #pragma unroll
    for (int i = 0; i < 32; i += 8) {
        float w = tile[tx][ty + i];                                    // transposed read
        __nv_bfloat16 hi = __float2bfloat16(w);
        __nv_bfloat16 lo = __float2bfloat16(w - __bfloat162float(hi));
        bh[(size_t)(n0 + ty + i) * 128 + k0 + tx] = hi;                // coalesced write
        bl[(size_t)(n0 + ty + i) * 128 + k0 + tx] = lo;
    }
}

// x (fp32) -> bf16 hi/lo plain rows
__global__ __launch_bounds__(256) void k_convert_x(const float* __restrict__ X, int n) {
    int warp = (blockIdx.x * blockDim.x + threadIdx.x) >> 5;
    int lane = threadIdx.x & 31;
    if (warp >= n) return;
    float4 v = ((const float4*)X)[(size_t)warp * 32 + lane];
    float4 lo4;
    unsigned long long hp = pack_hi4(v, &lo4);
    unsigned long long lp = pack_lo4(lo4);
    size_t off = (size_t)warp * 128 + lane * 4;
    *(unsigned long long*)(g_ah + off) = hp;
    *(unsigned long long*)(g_al + off) = lp;
}

// ---------------- HMMA GEMM: T = A @ W  (bf16 hi/lo 3-product, fp32 accum) ----------------
// Block: 128 rows x 128 cols, 8 warps each own 16 rows.
#define BPAD 72   // padded K-half row length (elements); conflict-free (4g+t) banks
__global__ __launch_bounds__(256) void k_gemm_mma(const __nv_bfloat16* __restrict__ Ah,
                                                  const __nv_bfloat16* __restrict__ Al,
                                                  const __nv_bfloat16* __restrict__ Bh,
                                                  const __nv_bfloat16* __restrict__ Bl,
                                                  float* __restrict__ T, int n) {
    __shared__ __align__(16) __nv_bfloat16 sBh[128][BPAD];
    __shared__ __align__(16) __nv_bfloat16 sBl[128][BPAD];

    int tid = threadIdx.x;
    int wid = tid >> 5;
    int lane = tid & 31;
    int g = lane >> 2;        // 0..7
    int t = lane & 3;         // 0..3
    int row_base = blockIdx.x * 128 + wid * 16;
    int r0 = row_base + g;    // rows r0 and r0+8

    float acc[16][4];
    #pragma unroll
    for (int nt = 0; nt < 16; nt++)
        #pragma unroll
        for (int j = 0; j < 4; j++) acc[nt][j] = 0.0f;

    #pragma unroll 1
    for (int kh = 0; kh < 2; kh++) {
        {
            const uint4* srcH = (const uint4*)(Bh + kh * 64);
            const uint4* srcL = (const uint4*)(Bl + kh * 64);
            #pragma unroll
            for (int i = tid; i < 128 * 8; i += 256) {
                int nrow = i >> 3, q = i & 7;
                *(uint4*)&sBh[nrow][q * 8] = srcH[nrow * 16 + q];
                *(uint4*)&sBl[nrow][q * 8] = srcL[nrow * 16 + q];
            }
        }
        __syncthreads();

        #pragma unroll
        for (int kc = 0; kc < 4; kc++) {
            int kabs = kh * 64 + kc * 16;
            const __nv_bfloat16* pa0 = Ah + (size_t)r0 * 128 + kabs + t * 2;
            const __nv_bfloat16* pa1 = pa0 + 8 * 128;
            const __nv_bfloat16* pl0 = Al + (size_t)r0 * 128 + kabs + t * 2;
            const __nv_bfloat16* pl1 = pl0 + 8 * 128;
            uint32_t ah0 = *(const uint32_t*)pa0;
            uint32_t ah1 = *(const uint32_t*)pa1;
            uint32_t ah2 = *(const uint32_t*)(pa0 + 8);
            uint32_t ah3 = *(const uint32_t*)(pa1 + 8);
            uint32_t al0 = *(const uint32_t*)pl0;
            uint32_t al1 = *(const uint32_t*)pl1;
            uint32_t al2 = *(const uint32_t*)(pl0 + 8);
            uint32_t al3 = *(const uint32_t*)(pl1 + 8);

            int ks = kc * 16 + t * 2;
            #pragma unroll
            for (int nt = 0; nt < 16; nt++) {
                int nrow = nt * 8 + g;
                uint32_t bh0 = *(const uint32_t*)&sBh[nrow][ks];
                uint32_t bh1 = *(const uint32_t*)&sBh[nrow][ks + 8];
                uint32_t bl0 = *(const uint32_t*)&sBl[nrow][ks];
                uint32_t bl1 = *(const uint32_t*)&sBl[nrow][ks + 8];
                mma_bf16(acc[nt], ah0, ah1, ah2, ah3, bh0, bh1);
                mma_bf16(acc[nt], ah0, ah1, ah2, ah3, bl0, bl1);
                mma_bf16(acc[nt], al0, al1, al2, al3, bh0, bh1);
            }
        }
        __syncthreads();
    }

    bool w0 = (r0 < n), w1 = (r0 + 8 < n);
    #pragma unroll
    for (int nt = 0; nt < 16; nt++) {
        int col = nt * 8 + t * 2;
        if (w0) *(float2*)(T + (size_t)r0 * 128 + col)       = make_float2(acc[nt][0], acc[nt][1]);
        if (w1) *(float2*)(T + (size_t)(r0 + 8) * 128 + col) = make_float2(acc[nt][2], acc[nt][3]);
    }
}

// ---------------- aggregate ----------------
// MODE 0: write bf16 hi/lo (feeds next GEMM); MODE 1: write fp32 H (feeds pool)
template<int MODE>
__global__ __launch_bounds__(256) void k_agg_t(const float* __restrict__ T,
                                               const float* __restrict__ bias,
                                               float* __restrict__ H, int n) {
    int warp = (blockIdx.x * blockDim.x + threadIdx.x) >> 5;
    int lane = threadIdx.x & 31;
    if (warp >= n) return;
    int v = warp;
    const float4* T4 = (const float4*)T;
    float dv = g_dinv[v];
    float4 acc = T4[(size_t)v * 32 + lane];
    float s = dv * dv;
    acc.x *= s; acc.y *= s; acc.z *= s; acc.w *= s;

    int start = g_indptr[v];
    int cnt = g_cursor[v];
    int i = 0;
    for (; i + 4 <= cnt; i += 4) {
        int s0 = g_src[start + i],     s1 = g_src[start + i + 1];
        int s2 = g_src[start + i + 2], s3 = g_src[start + i + 3];
        float w0 = g_wgt[start + i],     w1 = g_wgt[start + i + 1];
        float w2 = g_wgt[start + i + 2], w3 = g_wgt[start + i + 3];
        float4 x0 = T4[(size_t)s0 * 32 + lane];
        float4 x1 = T4[(size_t)s1 * 32 + lane];
        float4 x2 = T4[(size_t)s2 * 32 + lane];
        float4 x3 = T4[(size_t)s3 * 32 + lane];
        acc.x += w0 * x0.x + w1 * x1.x + w2 * x2.x + w3 * x3.x;
        acc.y += w0 * x0.y + w1 * x1.y + w2 * x2.y + w3 * x3.y;
        acc.z += w0 * x0.z + w1 * x1.z + w2 * x2.z + w3 * x3.z;
        acc.w += w0 * x0.w + w1 * x1.w + w2 * x2.w + w3 * x3.w;
    }
    for (; i < cnt; i++) {
        int s0 = g_src[start + i];
        float w0 = g_wgt[start + i];
        float4 x0 = T4[(size_t)s0 * 32 + lane];
        acc.x += w0 * x0.x; acc.y += w0 * x0.y; acc.z += w0 * x0.z; acc.w += w0 * x0.w;
    }
    float4 b = ((const float4*)bias)[lane];
    acc.x = fmaxf(acc.x + b.x, 0.f);
    acc.y = fmaxf(acc.y + b.y, 0.f);
    acc.z = fmaxf(acc.z + b.z, 0.f);
    acc.w = fmaxf(acc.w + b.w, 0.f);

    if (MODE == 1) {
        ((float4*)H)[(size_t)v * 32 + lane] = acc;
    } else {
        float4 lo4;
        unsigned long long hp = pack_hi4(acc, &lo4);
        unsigned long long lp = pack_lo4(lo4);
        size_t off = (size_t)v * 128 + lane * 4;
        *(unsigned long long*)(g_ah + off) = hp;
        *(unsigned long long*)(g_al + off) = lp;
    }
}

// ---------------- pool ----------------
__device__ __forceinline__ int lb_i(const int* a, int n, int key) {
    int lo = 0, hi = n;
    while (lo < hi) { int mid = (lo + hi) >> 1; if (a[mid] < key) lo = mid + 1; else hi = mid; }
    return lo;
}

__global__ void k_pool(const float* __restrict__ H, const int* __restrict__ batch, int n) {
    int g = blockIdx.x;
    __shared__ int s_lo, s_hi;
    if (threadIdx.x == 0) s_lo = lb_i(batch, n, g);
    if (threadIdx.x == 1) s_hi = lb_i(batch, n, g + 1);
    __syncthreads();
    int lo = s_lo, hi = s_hi;
    int k = threadIdx.x;
    float acc = 0.f;
    for (int v = lo; v < hi; v++) acc += H[(size_t)v * 128 + k];
    g_pool[g * 128 + k] = acc / fmaxf((float)(hi - lo), 1.0f);
}

__global__ void k_fc(const float* __restrict__ Wfc, const float* __restrict__ bfc,
                     float* __restrict__ out) {
    int g = blockIdx.x;
    int o = threadIdx.x;
    __shared__ float p[128];
    if (threadIdx.x < 128) p[threadIdx.x] = g_pool[g * 128 + threadIdx.x];
    __syncthreads();
    float acc = bfc[o];
    #pragma unroll 8
    for (int k = 0; k < 128; k++) acc += p[k] * Wfc[(size_t)k * 256 + o];
    out[(size_t)g * 256 + o] = acc;
}

// ---------------- launch ----------------
extern "C" void kernel_launch(void* const* d_in, const int* in_sizes, int n_in,
                              void* d_out, int out_size) {
    const float *x = 0, *Wfc = 0, *bfc = 0;
    const float *Wl[3] = {0, 0, 0};
    const float *bl[3] = {0, 0, 0};
    const int *ei = 0, *batch = 0;
    int nW = 0, nb = 0;
    for (int i = 0; i < n_in; i++) {
        int s = in_sizes[i];
        const void* p = d_in[i];
        if (s == NN * FD)            x = (const float*)p;
        else if (s == FD * HD) {     if (nW < 3) Wl[nW++] = (const float*)p; }
        else if (s == HD)        {   if (nb < 3) bl[nb++] = (const float*)p; }
        else if (s == HD * OD)       Wfc = (const float*)p;
        else if (s == OD)            bfc = (const float*)p;
        else if (s == 2 * EE)        ei = (const int*)p;
        else if (s == NN)            batch = (const int*)p;
    }
    float* out = (float*)d_out;

    int n = NN, e = EE;

    float *t_ptr, *h_ptr;
    cudaGetSymbolAddress((void**)&t_ptr, g_t);
    cudaGetSymbolAddress((void**)&h_ptr, g_h);
    __nv_bfloat16 *ah_ptr, *al_ptr, *bh_ptr, *bl_ptr;
    cudaGetSymbolAddress((void**)&ah_ptr, g_ah);
    cudaGetSymbolAddress((void**)&al_ptr, g_al);
    cudaGetSymbolAddress((void**)&bh_ptr, g_bh);
    cudaGetSymbolAddress((void**)&bl_ptr, g_bl);

    int nb_n = (n + 255) / 256;
    int nb_e = (e + 255) / 256;
    int nb_scan = (n + SCAN_B - 1) / SCAN_B;
    int nb_warp = (n * 32 + 255) / 256;

    // prep: degree + CSR by target
    k_init<<<nb_n, 256>>>(n);
    k_edges<<<nb_e, 256>>>(ei, e, n);
    k_scan1<<<nb_scan, SCAN_B>>>(n);      // scan + dinv fused
    k_scan2<<<1, 128>>>(nb_scan);
    k_scan3<<<nb_n, 256>>>(n);
    k_fill<<<nb_e, 256>>>(e);

    // weights + input -> bf16 hi/lo (parallel, coalesced)
    k_prep_w_all<<<dim3(4, 4, 3), dim3(32, 8)>>>(Wl[0], Wl[1], Wl[2]);
    k_convert_x<<<nb_warp, 256>>>(x, n);

    // layer 1
    k_gemm_mma<<<NT, 256>>>(ah_ptr, al_ptr, bh_ptr, bl_ptr, t_ptr, n);
    k_agg_t<0><<<nb_warp, 256>>>(t_ptr, bl[0], h_ptr, n);
    // layer 2
    k_gemm_mma<<<NT, 256>>>(ah_ptr, al_ptr, bh_ptr + 128 * 128, bl_ptr + 128 * 128, t_ptr, n);
    k_agg_t<0><<<nb_warp, 256>>>(t_ptr, bl[1], h_ptr, n);
    // layer 3
    k_gemm_mma<<<NT, 256>>>(ah_ptr, al_ptr, bh_ptr + 2 * 128 * 128, bl_ptr + 2 * 128 * 128, t_ptr, n);
    k_agg_t<1><<<nb_warp, 256>>>(t_ptr, bl[2], h_ptr, n);

    // pool + fc
    k_pool<<<GG, 128>>>(h_ptr, batch, n);
    k_fc<<<GG, 256>>>(Wfc, bfc, out);
}

// round 11
// speedup vs baseline: 1.4259x; 1.1357x over previous
#include <cuda_runtime.h>
#include <cuda_bf16.h>
#include <cuda_fp16.h>
#include <math.h>
#include <stdint.h>

// Problem constants
#define NN 100000
#define EE 1600000
#define FD 128
#define HD 128
#define OD 256
#define GG 256
#define NT 782              // ceil(NN/128) row tiles; NT*128 = 100096 rows

// ---------------- scratch ----------------
__device__ __half g_th[(size_t)NN * HD];                // transformed features (fp16)
__device__ __half g_hh[(size_t)NN * HD];                // final layer H (fp16)
__device__ __nv_bfloat16 g_ah[(size_t)NT * 128 * 128];  // A hi, plain [row*128+k]
__device__ __nv_bfloat16 g_al[(size_t)NT * 128 * 128];  // A lo
__device__ __nv_bfloat16 g_bh[3 * 128 * 128];           // W^T hi per layer [n*128+k]
__device__ __nv_bfloat16 g_bl[3 * 128 * 128];           // W^T lo
__device__ int   g_rowe[EE];
__device__ int   g_cole[EE];
__device__ int   g_src[EE];
__device__ float g_wgt[EE];
__device__ int   g_cnt[NN];
__device__ int   g_indptr[NN];
__device__ int   g_cursor[NN];
__device__ int   g_scan[NN];
__device__ int   g_bsum[256];
__device__ float g_dinv[NN];
__device__ float g_pool[GG * HD];

// ---------------- helpers ----------------
__device__ __forceinline__ unsigned long long pack_hi4(float4 v, float4* lo_out) {
    __nv_bfloat16 h0 = __float2bfloat16(v.x), h1 = __float2bfloat16(v.y);
    __nv_bfloat16 h2 = __float2bfloat16(v.z), h3 = __float2bfloat16(v.w);
    lo_out->x = v.x - __bfloat162float(h0);
    lo_out->y = v.y - __bfloat162float(h1);
    lo_out->z = v.z - __bfloat162float(h2);
    lo_out->w = v.w - __bfloat162float(h3);
    return (unsigned long long)__bfloat16_as_ushort(h0)
         | ((unsigned long long)__bfloat16_as_ushort(h1) << 16)
         | ((unsigned long long)__bfloat16_as_ushort(h2) << 32)
         | ((unsigned long long)__bfloat16_as_ushort(h3) << 48);
}
__device__ __forceinline__ unsigned long long pack_lo4(float4 v) {
    return (unsigned long long)__bfloat16_as_ushort(__float2bfloat16(v.x))
         | ((unsigned long long)__bfloat16_as_ushort(__float2bfloat16(v.y)) << 16)
         | ((unsigned long long)__bfloat16_as_ushort(__float2bfloat16(v.z)) << 32)
         | ((unsigned long long)__bfloat16_as_ushort(__float2bfloat16(v.w)) << 48);
}

__device__ __forceinline__ void mma_bf16(float* c, uint32_t a0, uint32_t a1,
                                         uint32_t a2, uint32_t a3,
                                         uint32_t b0, uint32_t b1) {
    asm volatile(
        "mma.sync.aligned.m16n8k16.row.col.f32.bf16.bf16.f32 "
        "{%0,%1,%2,%3}, {%4,%5,%6,%7}, {%8,%9}, {%0,%1,%2,%3};"
        : "+f"(c[0]), "+f"(c[1]), "+f"(c[2]), "+f"(c[3])
        : "r"(a0), "r"(a1), "r"(a2), "r"(a3), "r"(b0), "r"(b1));
}

__device__ __forceinline__ float4 unpack_h4(uint2 q) {
    __half2 h0 = *(__half2*)&q.x;
    __half2 h1 = *(__half2*)&q.y;
    float2 f0 = __half22float2(h0);
    float2 f1 = __half22float2(h1);
    return make_float4(f0.x, f0.y, f1.x, f1.y);
}

// ---------------- prep ----------------
__global__ void k_init(int n) {
    int i = blockIdx.x * blockDim.x + threadIdx.x;
    if (i < n) { g_cnt[i] = 0; g_cursor[i] = 0; }
}

// edge_index is int32 (JAX x64 disabled)
__global__ void k_edges(const int* __restrict__ ei, int e_total, int n) {
    int e = blockIdx.x * blockDim.x + threadIdx.x;
    if (e >= e_total) return;
    int r = ei[e];
    int c = ei[e_total + e];
    if ((unsigned)r >= (unsigned)n || (unsigned)c >= (unsigned)n) { g_rowe[e] = -1; g_cole[e] = -1; return; }
    g_rowe[e] = r; g_cole[e] = c;
    atomicAdd(&g_cnt[c], 1);
}

#define SCAN_B 1024
// block-level scan + per-node dinv (fused)
__global__ void k_scan1(int n) {
    __shared__ int s[SCAN_B];
    int tid = threadIdx.x;
    int v = blockIdx.x * SCAN_B + tid;
    int c = (v < n) ? g_cnt[v] : 0;
    if (v < n) g_dinv[v] = rsqrtf((float)(c + 1));   // +1 self-loop
    s[tid] = c;
    __syncthreads();
    #pragma unroll
    for (int off = 1; off < SCAN_B; off <<= 1) {
        int t = (tid >= off) ? s[tid - off] : 0;
        __syncthreads();
        s[tid] += t;
        __syncthreads();
    }
    if (v < n) g_scan[v] = s[tid] - c;
    if (tid == SCAN_B - 1) g_bsum[blockIdx.x] = s[tid];
}

// parallel exclusive scan of block sums (nblocks <= 128)
__global__ void k_scan2(int nblocks) {
    __shared__ int s[128];
    int t = threadIdx.x;
    int v = (t < nblocks) ? g_bsum[t] : 0;
    s[t] = v;
    __syncthreads();
    #pragma unroll
    for (int off = 1; off < 128; off <<= 1) {
        int u = (t >= off) ? s[t - off] : 0;
        __syncthreads();
        s[t] += u;
        __syncthreads();
    }
    if (t < nblocks) g_bsum[t] = s[t] - v;   // exclusive
}

__global__ void k_scan3(int n) {
    int v = blockIdx.x * blockDim.x + threadIdx.x;
    if (v < n) g_indptr[v] = g_scan[v] + g_bsum[v >> 10];
}

__global__ void k_fill(int e_total) {
    int e = blockIdx.x * blockDim.x + threadIdx.x;
    if (e >= e_total) return;
    int r = g_rowe[e], c = g_cole[e];
    if (r < 0 || c < 0) return;
    int slot = g_indptr[c] + atomicAdd(&g_cursor[c], 1);
    g_src[slot] = r;
    g_wgt[slot] = g_dinv[r] * g_dinv[c];
}

// W^T -> bf16 hi/lo for all 3 layers, coalesced smem-tile transpose.
__global__ void k_prep_w_all(const float* __restrict__ W0,
                             const float* __restrict__ W1,
                             const float* __restrict__ W2) {
    __shared__ float tile[32][33];
    int l = blockIdx.z;
    const float* W = (l == 0) ? W0 : ((l == 1) ? W1 : W2);
    int k0 = blockIdx.y * 32;
    int n0 = blockIdx.x * 32;
    int tx = threadIdx.x, ty = threadIdx.y;
    #pragma unroll
    for (int i = 0; i < 32; i += 8)
        tile[ty + i][tx] = W[(size_t)(k0 + ty + i) * 128 + n0 + tx];
    __syncthreads();
    __nv_bfloat16* bh = g_bh + (size_t)l * 16384;
    __nv_bfloat16* bl = g_bl + (size_t)l * 16384;
    #pragma unroll
    for (int i = 0; i < 32; i += 8) {
        float w = tile[tx][ty + i];
        __nv_bfloat16 hi = __float2bfloat16(w);
        __nv_bfloat16 lo = __float2bfloat16(w - __bfloat162float(hi));
        bh[(size_t)(n0 + ty + i) * 128 + k0 + tx] = hi;
        bl[(size_t)(n0 + ty + i) * 128 + k0 + tx] = lo;
    }
}

// x (fp32) -> bf16 hi/lo plain rows
__global__ __launch_bounds__(256) void k_convert_x(const float* __restrict__ X, int n) {
    int warp = (blockIdx.x * blockDim.x + threadIdx.x) >> 5;
    int lane = threadIdx.x & 31;
    if (warp >= n) return;
    float4 v = ((const float4*)X)[(size_t)warp * 32 + lane];
    float4 lo4;
    unsigned long long hp = pack_hi4(v, &lo4);
    unsigned long long lp = pack_lo4(lo4);
    size_t off = (size_t)warp * 128 + lane * 4;
    *(unsigned long long*)(g_ah + off) = hp;
    *(unsigned long long*)(g_al + off) = lp;
}

// ---------------- HMMA GEMM: T(fp16) = A @ W  (bf16 hi/lo 3-product, fp32 accum) ----------------
#define BPAD 72
__global__ __launch_bounds__(256) void k_gemm_mma(const __nv_bfloat16* __restrict__ Ah,
                                                  const __nv_bfloat16* __restrict__ Al,
                                                  const __nv_bfloat16* __restrict__ Bh,
                                                  const __nv_bfloat16* __restrict__ Bl,
                                                  __half* __restrict__ Th, int n) {
    __shared__ __align__(16) __nv_bfloat16 sBh[128][BPAD];
    __shared__ __align__(16) __nv_bfloat16 sBl[128][BPAD];

    int tid = threadIdx.x;
    int wid = tid >> 5;
    int lane = tid & 31;
    int g = lane >> 2;
    int t = lane & 3;
    int row_base = blockIdx.x * 128 + wid * 16;
    int r0 = row_base + g;

    float acc[16][4];
    #pragma unroll
    for (int nt = 0; nt < 16; nt++)
        #pragma unroll
        for (int j = 0; j < 4; j++) acc[nt][j] = 0.0f;

    #pragma unroll 1
    for (int kh = 0; kh < 2; kh++) {
        {
            const uint4* srcH = (const uint4*)(Bh + kh * 64);
            const uint4* srcL = (const uint4*)(Bl + kh * 64);
            #pragma unroll
            for (int i = tid; i < 128 * 8; i += 256) {
                int nrow = i >> 3, q = i & 7;
                *(uint4*)&sBh[nrow][q * 8] = srcH[nrow * 16 + q];
                *(uint4*)&sBl[nrow][q * 8] = srcL[nrow * 16 + q];
            }
        }
        __syncthreads();

        #pragma unroll
        for (int kc = 0; kc < 4; kc++) {
            int kabs = kh * 64 + kc * 16;
            const __nv_bfloat16* pa0 = Ah + (size_t)r0 * 128 + kabs + t * 2;
            const __nv_bfloat16* pa1 = pa0 + 8 * 128;
            const __nv_bfloat16* pl0 = Al + (size_t)r0 * 128 + kabs + t * 2;
            const __nv_bfloat16* pl1 = pl0 + 8 * 128;
            uint32_t ah0 = *(const uint32_t*)pa0;
            uint32_t ah1 = *(const uint32_t*)pa1;
            uint32_t ah2 = *(const uint32_t*)(pa0 + 8);
            uint32_t ah3 = *(const uint32_t*)(pa1 + 8);
            uint32_t al0 = *(const uint32_t*)pl0;
            uint32_t al1 = *(const uint32_t*)pl1;
            uint32_t al2 = *(const uint32_t*)(pl0 + 8);
            uint32_t al3 = *(const uint32_t*)(pl1 + 8);

            int ks = kc * 16 + t * 2;
            #pragma unroll
            for (int nt = 0; nt < 16; nt++) {
                int nrow = nt * 8 + g;
                uint32_t bh0 = *(const uint32_t*)&sBh[nrow][ks];
                uint32_t bh1 = *(const uint32_t*)&sBh[nrow][ks + 8];
                uint32_t bl0 = *(const uint32_t*)&sBl[nrow][ks];
                uint32_t bl1 = *(const uint32_t*)&sBl[nrow][ks + 8];
                mma_bf16(acc[nt], ah0, ah1, ah2, ah3, bh0, bh1);
                mma_bf16(acc[nt], ah0, ah1, ah2, ah3, bl0, bl1);
                mma_bf16(acc[nt], al0, al1, al2, al3, bh0, bh1);
            }
        }
        __syncthreads();
    }

    bool w0 = (r0 < n), w1 = (r0 + 8 < n);
    #pragma unroll
    for (int nt = 0; nt < 16; nt++) {
        int col = nt * 8 + t * 2;
        if (w0) *(__half2*)(Th + (size_t)r0 * 128 + col)
                    = __floats2half2_rn(acc[nt][0], acc[nt][1]);
        if (w1) *(__half2*)(Th + (size_t)(r0 + 8) * 128 + col)
                    = __floats2half2_rn(acc[nt][2], acc[nt][3]);
    }
}

// ---------------- aggregate (fp16 gather) ----------------
// MODE 0: write bf16 hi/lo (feeds next GEMM); MODE 1: write fp16 H (feeds pool)
template<int MODE>
__global__ __launch_bounds__(256) void k_agg_t(const __half* __restrict__ Th,
                                               const float* __restrict__ bias, int n) {
    int warp = (blockIdx.x * blockDim.x + threadIdx.x) >> 5;
    int lane = threadIdx.x & 31;
    if (warp >= n) return;
    int v = warp;
    const uint2* T2 = (const uint2*)Th;   // 4 halves per lane, row stride 32 uint2
    float dv = g_dinv[v];
    float s = dv * dv;
    float4 self = unpack_h4(T2[(size_t)v * 32 + lane]);
    float4 acc = make_float4(self.x * s, self.y * s, self.z * s, self.w * s);

    int start = g_indptr[v];
    int cnt = g_cursor[v];
    int i = 0;
    for (; i + 4 <= cnt; i += 4) {
        int s0 = g_src[start + i],     s1 = g_src[start + i + 1];
        int s2 = g_src[start + i + 2], s3 = g_src[start + i + 3];
        float w0 = g_wgt[start + i],     w1 = g_wgt[start + i + 1];
        float w2 = g_wgt[start + i + 2], w3 = g_wgt[start + i + 3];
        uint2 q0 = T2[(size_t)s0 * 32 + lane];
        uint2 q1 = T2[(size_t)s1 * 32 + lane];
        uint2 q2 = T2[(size_t)s2 * 32 + lane];
        uint2 q3 = T2[(size_t)s3 * 32 + lane];
        float4 x0 = unpack_h4(q0), x1 = unpack_h4(q1);
        float4 x2 = unpack_h4(q2), x3 = unpack_h4(q3);
        acc.x += w0 * x0.x + w1 * x1.x + w2 * x2.x + w3 * x3.x;
        acc.y += w0 * x0.y + w1 * x1.y + w2 * x2.y + w3 * x3.y;
        acc.z += w0 * x0.z + w1 * x1.z + w2 * x2.z + w3 * x3.z;
        acc.w += w0 * x0.w + w1 * x1.w + w2 * x2.w + w3 * x3.w;
    }
    for (; i < cnt; i++) {
        int s0 = g_src[start + i];
        float w0 = g_wgt[start + i];
        float4 x0 = unpack_h4(T2[(size_t)s0 * 32 + lane]);
        acc.x += w0 * x0.x; acc.y += w0 * x0.y; acc.z += w0 * x0.z; acc.w += w0 * x0.w;
    }
    float4 b = ((const float4*)bias)[lane];
    acc.x = fmaxf(acc.x + b.x, 0.f);
    acc.y = fmaxf(acc.y + b.y, 0.f);
    acc.z = fmaxf(acc.z + b.z, 0.f);
    acc.w = fmaxf(acc.w + b.w, 0.f);

    if (MODE == 1) {
        uint2 q;
        *(__half2*)&q.x = __floats2half2_rn(acc.x, acc.y);
        *(__half2*)&q.y = __floats2half2_rn(acc.z, acc.w);
        ((uint2*)g_hh)[(size_t)v * 32 + lane] = q;
    } else {
        float4 lo4;
        unsigned long long hp = pack_hi4(acc, &lo4);
        unsigned long long lp = pack_lo4(lo4);
        size_t off = (size_t)v * 128 + lane * 4;
        *(unsigned long long*)(g_ah + off) = hp;
        *(unsigned long long*)(g_al + off) = lp;
    }
}

// ---------------- pool ----------------
__device__ __forceinline__ int lb_i(const int* a, int n, int key) {
    int lo = 0, hi = n;
    while (lo < hi) { int mid = (lo + hi) >> 1; if (a[mid] < key) lo = mid + 1; else hi = mid; }
    return lo;
}

__global__ void k_pool(const int* __restrict__ batch, int n) {
    int g = blockIdx.x;
    __shared__ int s_lo, s_hi;
    if (threadIdx.x == 0) s_lo = lb_i(batch, n, g);
    if (threadIdx.x == 1) s_hi = lb_i(batch, n, g + 1);
    __syncthreads();
    int lo = s_lo, hi = s_hi;
    int k = threadIdx.x;
    float acc = 0.f;
    for (int v = lo; v < hi; v++) acc += __half2float(g_hh[(size_t)v * 128 + k]);
    g_pool[g * 128 + k] = acc / fmaxf((float)(hi - lo), 1.0f);
}

__global__ void k_fc(const float* __restrict__ Wfc, const float* __restrict__ bfc,
                     float* __restrict__ out) {
    int g = blockIdx.x;
    int o = threadIdx.x;
    __shared__ float p[128];
    if (threadIdx.x < 128) p[threadIdx.x] = g_pool[g * 128 + threadIdx.x];
    __syncthreads();
    float acc = bfc[o];
    #pragma unroll 8
    for (int k = 0; k < 128; k++) acc += p[k] * Wfc[(size_t)k * 256 + o];
    out[(size_t)g * 256 + o] = acc;
}

// ---------------- launch ----------------
extern "C" void kernel_launch(void* const* d_in, const int* in_sizes, int n_in,
                              void* d_out, int out_size) {
    const float *x = 0, *Wfc = 0, *bfc = 0;
    const float *Wl[3] = {0, 0, 0};
    const float *bl[3] = {0, 0, 0};
    const int *ei = 0, *batch = 0;
    int nW = 0, nb = 0;
    for (int i = 0; i < n_in; i++) {
        int s = in_sizes[i];
        const void* p = d_in[i];
        if (s == NN * FD)            x = (const float*)p;
        else if (s == FD * HD) {     if (nW < 3) Wl[nW++] = (const float*)p; }
        else if (s == HD)        {   if (nb < 3) bl[nb++] = (const float*)p; }
        else if (s == HD * OD)       Wfc = (const float*)p;
        else if (s == OD)            bfc = (const float*)p;
        else if (s == 2 * EE)        ei = (const int*)p;
        else if (s == NN)            batch = (const int*)p;
    }
    float* out = (float*)d_out;

    int n = NN, e = EE;

    __half* th_ptr;
    cudaGetSymbolAddress((void**)&th_ptr, g_th);
    __nv_bfloat16 *ah_ptr, *al_ptr, *bh_ptr, *bl_ptr;
    cudaGetSymbolAddress((void**)&ah_ptr, g_ah);
    cudaGetSymbolAddress((void**)&al_ptr, g_al);
    cudaGetSymbolAddress((void**)&bh_ptr, g_bh);
    cudaGetSymbolAddress((void**)&bl_ptr, g_bl);

    int nb_n = (n + 255) / 256;
    int nb_e = (e + 255) / 256;
    int nb_scan = (n + SCAN_B - 1) / SCAN_B;
    int nb_warp = (n * 32 + 255) / 256;

    // prep: degree + CSR by target
    k_init<<<nb_n, 256>>>(n);
    k_edges<<<nb_e, 256>>>(ei, e, n);
    k_scan1<<<nb_scan, SCAN_B>>>(n);
    k_scan2<<<1, 128>>>(nb_scan);
    k_scan3<<<nb_n, 256>>>(n);
    k_fill<<<nb_e, 256>>>(e);

    // weights + input -> bf16 hi/lo
    k_prep_w_all<<<dim3(4, 4, 3), dim3(32, 8)>>>(Wl[0], Wl[1], Wl[2]);
    k_convert_x<<<nb_warp, 256>>>(x, n);

    // layer 1
    k_gemm_mma<<<NT, 256>>>(ah_ptr, al_ptr, bh_ptr, bl_ptr, th_ptr, n);
    k_agg_t<0><<<nb_warp, 256>>>(th_ptr, bl[0], n);
    // layer 2
    k_gemm_mma<<<NT, 256>>>(ah_ptr, al_ptr, bh_ptr + 16384, bl_ptr + 16384, th_ptr, n);
    k_agg_t<0><<<nb_warp, 256>>>(th_ptr, bl[1], n);
    // layer 3
    k_gemm_mma<<<NT, 256>>>(ah_ptr, al_ptr, bh_ptr + 32768, bl_ptr + 32768, th_ptr, n);
    k_agg_t<1><<<nb_warp, 256>>>(th_ptr, bl[2], n);

    // pool + fc
    k_pool<<<GG, 128>>>(batch, n);
    k_fc<<<GG, 256>>>(Wfc, bfc, out);
}

// round 13
// speedup vs baseline: 1.5609x; 1.0947x over previous
#include <cuda_runtime.h>
#include <cuda_bf16.h>
#include <cuda_fp16.h>
#include <math.h>
#include <stdint.h>

// Problem constants
#define NN 100000
#define EE 1600000
#define FD 128
#define HD 128
#define OD 256
#define GG 256
#define NT 782              // ceil(NN/128); NT*128 = 100096

// ---------------- scratch ----------------
__device__ __half g_th[(size_t)NN * HD];                // transformed features (fp16)
__device__ __half g_hh[(size_t)NN * HD];                // final layer H (fp16)
__device__ __nv_bfloat16 g_ah[(size_t)NT * 128 * 128];  // A hi [row*128+k]
__device__ __nv_bfloat16 g_al[(size_t)NT * 128 * 128];  // A lo
__device__ __nv_bfloat16 g_bh[3 * 128 * 128];           // W^T hi per layer [n*128+k]
__device__ __nv_bfloat16 g_bl[3 * 128 * 128];           // W^T lo
__device__ int   g_src[EE];
__device__ float g_wgt[EE];
__device__ int   g_cnt[NN];
__device__ int   g_cursor[NN];
__device__ int   g_scan[NN];
__device__ int   g_bsum[256];
__device__ float g_dinv[NN];

// ---------------- helpers ----------------
__device__ __forceinline__ uint32_t pack2_hl(float a, float b, uint32_t* lo) {
    __nv_bfloat16 ha = __float2bfloat16(a), hb = __float2bfloat16(b);
    float ra = a - __bfloat162float(ha);
    float rb = b - __bfloat162float(hb);
    *lo = (uint32_t)__bfloat16_as_ushort(__float2bfloat16(ra))
        | ((uint32_t)__bfloat16_as_ushort(__float2bfloat16(rb)) << 16);
    return (uint32_t)__bfloat16_as_ushort(ha)
         | ((uint32_t)__bfloat16_as_ushort(hb) << 16);
}

__device__ __forceinline__ unsigned long long pack_hi4(float4 v, float4* lo_out) {
    __nv_bfloat16 h0 = __float2bfloat16(v.x), h1 = __float2bfloat16(v.y);
    __nv_bfloat16 h2 = __float2bfloat16(v.z), h3 = __float2bfloat16(v.w);
    lo_out->x = v.x - __bfloat162float(h0);
    lo_out->y = v.y - __bfloat162float(h1);
    lo_out->z = v.z - __bfloat162float(h2);
    lo_out->w = v.w - __bfloat162float(h3);
    return (unsigned long long)__bfloat16_as_ushort(h0)
         | ((unsigned long long)__bfloat16_as_ushort(h1) << 16)
         | ((unsigned long long)__bfloat16_as_ushort(h2) << 32)
         | ((unsigned long long)__bfloat16_as_ushort(h3) << 48);
}
__device__ __forceinline__ unsigned long long pack_lo4(float4 v) {
    return (unsigned long long)__bfloat16_as_ushort(__float2bfloat16(v.x))
         | ((unsigned long long)__bfloat16_as_ushort(__float2bfloat16(v.y)) << 16)
         | ((unsigned long long)__bfloat16_as_ushort(__float2bfloat16(v.z)) << 32)
         | ((unsigned long long)__bfloat16_as_ushort(__float2bfloat16(v.w)) << 48);
}

__device__ __forceinline__ void mma_bf16(float* c, uint32_t a0, uint32_t a1,
                                         uint32_t a2, uint32_t a3,
                                         uint32_t b0, uint32_t b1) {
    asm volatile(
        "mma.sync.aligned.m16n8k16.row.col.f32.bf16.bf16.f32 "
        "{%0,%1,%2,%3}, {%4,%5,%6,%7}, {%8,%9}, {%0,%1,%2,%3};"
        : "+f"(c[0]), "+f"(c[1]), "+f"(c[2]), "+f"(c[3])
        : "r"(a0), "r"(a1), "r"(a2), "r"(a3), "r"(b0), "r"(b1));
}

__device__ __forceinline__ float4 unpack_h4(uint2 q) {
    __half2 h0 = *(__half2*)&q.x;
    __half2 h1 = *(__half2*)&q.y;
    float2 f0 = __half22float2(h0);
    float2 f1 = __half22float2(h1);
    return make_float4(f0.x, f0.y, f1.x, f1.y);
}

// ---------------- prep (side stream) ----------------
// edge_index is int32 (JAX x64 disabled)
__global__ void k_edges(const int* __restrict__ ei, int e_total, int n) {
    int e = blockIdx.x * blockDim.x + threadIdx.x;
    if (e >= e_total) return;
    int r = ei[e];
    int c = ei[e_total + e];
    if ((unsigned)r >= (unsigned)n || (unsigned)c >= (unsigned)n) return;
    atomicAdd(&g_cnt[c], 1);
}

#define SCAN_B 1024
__global__ void k_scan1(int n) {
    __shared__ int s[SCAN_B];
    int tid = threadIdx.x;
    int v = blockIdx.x * SCAN_B + tid;
    int c = (v < n) ? g_cnt[v] : 0;
    if (v < n) g_dinv[v] = rsqrtf((float)(c + 1));   // +1 self-loop
    s[tid] = c;
    __syncthreads();
    #pragma unroll
    for (int off = 1; off < SCAN_B; off <<= 1) {
        int t = (tid >= off) ? s[tid - off] : 0;
        __syncthreads();
        s[tid] += t;
        __syncthreads();
    }
    if (v < n) g_scan[v] = s[tid] - c;    // exclusive within block
    if (tid == SCAN_B - 1) g_bsum[blockIdx.x] = s[tid];
}

__global__ void k_scan2(int nblocks) {
    __shared__ int s[128];
    int t = threadIdx.x;
    int v = (t < nblocks) ? g_bsum[t] : 0;
    s[t] = v;
    __syncthreads();
    #pragma unroll
    for (int off = 1; off < 128; off <<= 1) {
        int u = (t >= off) ? s[t - off] : 0;
        __syncthreads();
        s[t] += u;
        __syncthreads();
    }
    if (t < nblocks) g_bsum[t] = s[t] - v;   // exclusive
}

__global__ void k_fill(const int* __restrict__ ei, int e_total, int n) {
    int e = blockIdx.x * blockDim.x + threadIdx.x;
    if (e >= e_total) return;
    int r = ei[e];
    int c = ei[e_total + e];
    if ((unsigned)r >= (unsigned)n || (unsigned)c >= (unsigned)n) return;
    int base = g_scan[c] + g_bsum[c >> 10];
    int slot = base + atomicAdd(&g_cursor[c], 1);
    g_src[slot] = r;
    g_wgt[slot] = g_dinv[r] * g_dinv[c];
}

// W^T -> bf16 hi/lo, coalesced smem-tile transpose (all 3 layers)
__global__ void k_prep_w_all(const float* __restrict__ W0,
                             const float* __restrict__ W1,
                             const float* __restrict__ W2) {
    __shared__ float tile[32][33];
    int l = blockIdx.z;
    const float* W = (l == 0) ? W0 : ((l == 1) ? W1 : W2);
    int k0 = blockIdx.y * 32;
    int n0 = blockIdx.x * 32;
    int tx = threadIdx.x, ty = threadIdx.y;
    #pragma unroll
    for (int i = 0; i < 32; i += 8)
        tile[ty + i][tx] = W[(size_t)(k0 + ty + i) * 128 + n0 + tx];
    __syncthreads();
    __nv_bfloat16* bh = g_bh + (size_t)l * 16384;
    __nv_bfloat16* bl = g_bl + (size_t)l * 16384;
    #pragma unroll
    for (int i = 0; i < 32; i += 8) {
        float w = tile[tx][ty + i];
        __nv_bfloat16 hi = __float2bfloat16(w);
        __nv_bfloat16 lo = __float2bfloat16(w - __bfloat162float(hi));
        bh[(size_t)(n0 + ty + i) * 128 + k0 + tx] = hi;
        bl[(size_t)(n0 + ty + i) * 128 + k0 + tx] = lo;
    }
}

// ---------------- HMMA GEMM: T(fp16) = A @ W ----------------
// SRC 0: A = fp32 X (split in-register); SRC 1: A = g_ah/g_al bf16 pair
#define BPAD 72
template<int SRC>
__global__ __launch_bounds__(256) void k_gemm_t(const float* __restrict__ X,
                                                const __nv_bfloat16* __restrict__ Ah,
                                                const __nv_bfloat16* __restrict__ Al,
                                                const __nv_bfloat16* __restrict__ Bh,
                                                const __nv_bfloat16* __restrict__ Bl,
                                                __half* __restrict__ Th, int n) {
    __shared__ __align__(16) __nv_bfloat16 sBh[128][BPAD];
    __shared__ __align__(16) __nv_bfloat16 sBl[128][BPAD];

    int tid = threadIdx.x;
    int wid = tid >> 5;
    int lane = tid & 31;
    int g = lane >> 2;
    int t = lane & 3;
    int row_base = blockIdx.x * 128 + wid * 16;
    int r0 = row_base + g;

    float acc[16][4];
    #pragma unroll
    for (int nt = 0; nt < 16; nt++)
        #pragma unroll
        for (int j = 0; j < 4; j++) acc[nt][j] = 0.0f;

    #pragma unroll 1
    for (int kh = 0; kh < 2; kh++) {
        {
            const uint4* srcH = (const uint4*)(Bh + kh * 64);
            const uint4* srcL = (const uint4*)(Bl + kh * 64);
            #pragma unroll
            for (int i = tid; i < 128 * 8; i += 256) {
                int nrow = i >> 3, q = i & 7;
                *(uint4*)&sBh[nrow][q * 8] = srcH[nrow * 16 + q];
                *(uint4*)&sBl[nrow][q * 8] = srcL[nrow * 16 + q];
            }
        }
        __syncthreads();

        #pragma unroll
        for (int kc = 0; kc < 4; kc++) {
            int kabs = kh * 64 + kc * 16;
            uint32_t ah0, ah1, ah2, ah3, al0, al1, al2, al3;
            if (SRC == 0) {
                int rA = (r0 < n) ? r0 : (n - 1);
                int rB = (r0 + 8 < n) ? (r0 + 8) : (n - 1);
                const float* px0 = X + (size_t)rA * 128 + kabs + t * 2;
                const float* px1 = X + (size_t)rB * 128 + kabs + t * 2;
                float2 f0 = *(const float2*)px0;
                float2 f1 = *(const float2*)px1;
                float2 f2 = *(const float2*)(px0 + 8);
                float2 f3 = *(const float2*)(px1 + 8);
                ah0 = pack2_hl(f0.x, f0.y, &al0);
                ah1 = pack2_hl(f1.x, f1.y, &al1);
                ah2 = pack2_hl(f2.x, f2.y, &al2);
                ah3 = pack2_hl(f3.x, f3.y, &al3);
            } else {
                const __nv_bfloat16* pa0 = Ah + (size_t)r0 * 128 + kabs + t * 2;
                const __nv_bfloat16* pa1 = pa0 + 8 * 128;
                const __nv_bfloat16* pl0 = Al + (size_t)r0 * 128 + kabs + t * 2;
                const __nv_bfloat16* pl1 = pl0 + 8 * 128;
                ah0 = *(const uint32_t*)pa0;
                ah1 = *(const uint32_t*)pa1;
                ah2 = *(const uint32_t*)(pa0 + 8);
                ah3 = *(const uint32_t*)(pa1 + 8);
                al0 = *(const uint32_t*)pl0;
                al1 = *(const uint32_t*)pl1;
                al2 = *(const uint32_t*)(pl0 + 8);
                al3 = *(const uint32_t*)(pl1 + 8);
            }

            int ks = kc * 16 + t * 2;
            #pragma unroll
            for (int nt = 0; nt < 16; nt++) {
                int nrow = nt * 8 + g;
                uint32_t bh0 = *(const uint32_t*)&sBh[nrow][ks];
                uint32_t bh1 = *(const uint32_t*)&sBh[nrow][ks + 8];
                uint32_t bl0 = *(const uint32_t*)&sBl[nrow][ks];
                uint32_t bl1 = *(const uint32_t*)&sBl[nrow][ks + 8];
                mma_bf16(acc[nt], ah0, ah1, ah2, ah3, bh0, bh1);
                mma_bf16(acc[nt], ah0, ah1, ah2, ah3, bl0, bl1);
                mma_bf16(acc[nt], al0, al1, al2, al3, bh0, bh1);
            }
        }
        __syncthreads();
    }

    bool w0 = (r0 < n), w1 = (r0 + 8 < n);
    #pragma unroll
    for (int nt = 0; nt < 16; nt++) {
        int col = nt * 8 + t * 2;
        if (w0) *(__half2*)(Th + (size_t)r0 * 128 + col)
                    = __floats2half2_rn(acc[nt][0], acc[nt][1]);
        if (w1) *(__half2*)(Th + (size_t)(r0 + 8) * 128 + col)
                    = __floats2half2_rn(acc[nt][2], acc[nt][3]);
    }
}

// ---------------- aggregate (fp16 gather) ----------------
// MODE 0: write bf16 hi/lo (feeds next GEMM); MODE 1: write fp16 H (feeds pool)
template<int MODE>
__global__ __launch_bounds__(256) void k_agg_t(const __half* __restrict__ Th,
                                               const float* __restrict__ bias, int n) {
    int warp = (blockIdx.x * blockDim.x + threadIdx.x) >> 5;
    int lane = threadIdx.x & 31;
    if (warp >= n) return;
    int v = warp;
    const uint2* T2 = (const uint2*)Th;
    float dv = g_dinv[v];
    float s = dv * dv;
    float4 self = unpack_h4(T2[(size_t)v * 32 + lane]);
    float4 acc = make_float4(self.x * s, self.y * s, self.z * s, self.w * s);

    int start = g_scan[v] + g_bsum[v >> 10];
    int cnt = g_cursor[v];
    int i = 0;
    for (; i + 4 <= cnt; i += 4) {
        int s0 = g_src[start + i],     s1 = g_src[start + i + 1];
        int s2 = g_src[start + i + 2], s3 = g_src[start + i + 3];
        float w0 = g_wgt[start + i],     w1 = g_wgt[start + i + 1];
        float w2 = g_wgt[start + i + 2], w3 = g_wgt[start + i + 3];
        uint2 q0 = T2[(size_t)s0 * 32 + lane];
        uint2 q1 = T2[(size_t)s1 * 32 + lane];
        uint2 q2 = T2[(size_t)s2 * 32 + lane];
        uint2 q3 = T2[(size_t)s3 * 32 + lane];
        float4 x0 = unpack_h4(q0), x1 = unpack_h4(q1);
        float4 x2 = unpack_h4(q2), x3 = unpack_h4(q3);
        acc.x += w0 * x0.x + w1 * x1.x + w2 * x2.x + w3 * x3.x;
        acc.y += w0 * x0.y + w1 * x1.y + w2 * x2.y + w3 * x3.y;
        acc.z += w0 * x0.z + w1 * x1.z + w2 * x2.z + w3 * x3.z;
        acc.w += w0 * x0.w + w1 * x1.w + w2 * x2.w + w3 * x3.w;
    }
    for (; i < cnt; i++) {
        int s0 = g_src[start + i];
        float w0 = g_wgt[start + i];
        float4 x0 = unpack_h4(T2[(size_t)s0 * 32 + lane]);
        acc.x += w0 * x0.x; acc.y += w0 * x0.y; acc.z += w0 * x0.z; acc.w += w0 * x0.w;
    }
    float4 b = ((const float4*)bias)[lane];
    acc.x = fmaxf(acc.x + b.x, 0.f);
    acc.y = fmaxf(acc.y + b.y, 0.f);
    acc.z = fmaxf(acc.z + b.z, 0.f);
    acc.w = fmaxf(acc.w + b.w, 0.f);

    if (MODE == 1) {
        uint2 q;
        *(__half2*)&q.x = __floats2half2_rn(acc.x, acc.y);
        *(__half2*)&q.y = __floats2half2_rn(acc.z, acc.w);
        ((uint2*)g_hh)[(size_t)v * 32 + lane] = q;
    } else {
        float4 lo4;
        unsigned long long hp = pack_hi4(acc, &lo4);
        unsigned long long lp = pack_lo4(lo4);
        size_t off = (size_t)v * 128 + lane * 4;
        *(unsigned long long*)(g_ah + off) = hp;
        *(unsigned long long*)(g_al + off) = lp;
    }
}

// ---------------- fused pool + fc ----------------
__device__ __forceinline__ int lb_i(const int* a, int n, int key) {
    int lo = 0, hi = n;
    while (lo < hi) { int mid = (lo + hi) >> 1; if (a[mid] < key) lo = mid + 1; else hi = mid; }
    return lo;
}

__global__ __launch_bounds__(256) void k_poolfc(const int* __restrict__ batch,
                                                const float* __restrict__ Wfc,
                                                const float* __restrict__ bfc,
                                                float* __restrict__ out, int n) {
    int g = blockIdx.x;
    int tid = threadIdx.x;
    __shared__ int s_lo, s_hi;
    __shared__ float part[2][128];
    __shared__ float p[128];
    if (tid == 0) s_lo = lb_i(batch, n, g);
    if (tid == 1) s_hi = lb_i(batch, n, g + 1);
    __syncthreads();
    int lo = s_lo, hi = s_hi;
    int k = tid & 127;
    int half = tid >> 7;
    int mid = (lo + hi) >> 1;
    int a = half ? mid : lo;
    int b = half ? hi : mid;
    float acc = 0.f;
    for (int v = a; v < b; v++) acc += __half2float(g_hh[(size_t)v * 128 + k]);
    part[half][k] = acc;
    __syncthreads();
    if (tid < 128)
        p[tid] = (part[0][tid] + part[1][tid]) / fmaxf((float)(hi - lo), 1.0f);
    __syncthreads();
    int o = tid;
    float oacc = bfc[o];
    #pragma unroll 8
    for (int kk = 0; kk < 128; kk++) oacc += p[kk] * Wfc[(size_t)kk * 256 + o];
    out[(size_t)g * 256 + o] = oacc;
}

// ---------------- launch ----------------
extern "C" void kernel_launch(void* const* d_in, const int* in_sizes, int n_in,
                              void* d_out, int out_size) {
    const float *x = 0, *Wfc = 0, *bfc = 0;
    const float *Wl[3] = {0, 0, 0};
    const float *bl[3] = {0, 0, 0};
    const int *ei = 0, *batch = 0;
    int nW = 0, nb = 0;
    for (int i = 0; i < n_in; i++) {
        int s = in_sizes[i];
        const void* p = d_in[i];
        if (s == NN * FD)            x = (const float*)p;
        else if (s == FD * HD) {     if (nW < 3) Wl[nW++] = (const float*)p; }
        else if (s == HD)        {   if (nb < 3) bl[nb++] = (const float*)p; }
        else if (s == HD * OD)       Wfc = (const float*)p;
        else if (s == OD)            bfc = (const float*)p;
        else if (s == 2 * EE)        ei = (const int*)p;
        else if (s == NN)            batch = (const int*)p;
    }
    float* out = (float*)d_out;

    int n = NN, e = EE;

    // lazy host-side resources (no device allocations)
    static cudaStream_t s1 = 0;
    static cudaEvent_t evFork = 0, evJoin = 0;
    if (!s1) {
        cudaStreamCreateWithFlags(&s1, cudaStreamNonBlocking);
        cudaEventCreateWithFlags(&evFork, cudaEventDisableTiming);
        cudaEventCreateWithFlags(&evJoin, cudaEventDisableTiming);
    }

    __half* th_ptr;
    cudaGetSymbolAddress((void**)&th_ptr, g_th);
    __nv_bfloat16 *ah_ptr, *al_ptr, *bh_ptr, *bl_ptr;
    cudaGetSymbolAddress((void**)&ah_ptr, g_ah);
    cudaGetSymbolAddress((void**)&al_ptr, g_al);
    cudaGetSymbolAddress((void**)&bh_ptr, g_bh);
    cudaGetSymbolAddress((void**)&bl_ptr, g_bl);
    int *cnt_ptr, *cur_ptr;
    cudaGetSymbolAddress((void**)&cnt_ptr, g_cnt);
    cudaGetSymbolAddress((void**)&cur_ptr, g_cursor);

    int nb_e = (e + 255) / 256;
    int nb_scan = (n + SCAN_B - 1) / SCAN_B;
    int nb_warp = (n * 32 + 255) / 256;

    // ---- fork: CSR prep on side stream s1 ----
    cudaEventRecord(evFork, 0);
    cudaStreamWaitEvent(s1, evFork, 0);
    cudaMemsetAsync(cnt_ptr, 0, (size_t)n * sizeof(int), s1);
    cudaMemsetAsync(cur_ptr, 0, (size_t)n * sizeof(int), s1);
    k_edges<<<nb_e, 256, 0, s1>>>(ei, e, n);
    k_scan1<<<nb_scan, SCAN_B, 0, s1>>>(n);
    k_scan2<<<1, 128, 0, s1>>>(nb_scan);
    k_fill<<<nb_e, 256, 0, s1>>>(ei, e, n);
    cudaEventRecord(evJoin, s1);

    // ---- main stream: weights + GEMM1 (reads fp32 x directly) ----
    k_prep_w_all<<<dim3(4, 4, 3), dim3(32, 8)>>>(Wl[0], Wl[1], Wl[2]);
    k_gemm_t<0><<<NT, 256>>>(x, ah_ptr, al_ptr, bh_ptr, bl_ptr, th_ptr, n);

    // ---- join ----
    cudaStreamWaitEvent(0, evJoin, 0);

    // layer 1 agg, then layers 2/3
    k_agg_t<0><<<nb_warp, 256>>>(th_ptr, bl[0], n);
    k_gemm_t<1><<<NT, 256>>>(x, ah_ptr, al_ptr, bh_ptr + 16384, bl_ptr + 16384, th_ptr, n);
    k_agg_t<0><<<nb_warp, 256>>>(th_ptr, bl[1], n);
    k_gemm_t<1><<<NT, 256>>>(x, ah_ptr, al_ptr, bh_ptr + 32768, bl_ptr + 32768, th_ptr, n);
    k_agg_t<1><<<nb_warp, 256>>>(th_ptr, bl[2], n);

    // fused pool + fc
    k_poolfc<<<GG, 256>>>(batch, Wfc, bfc, out, n);
}

// round 16
// speedup vs baseline: 1.5700x; 1.0058x over previous
#include <cuda_runtime.h>
#include <cuda_bf16.h>
#include <cuda_fp16.h>
#include <math.h>
#include <stdint.h>

// Problem constants
#define NN 100000
#define EE 1600000
#define FD 128
#define HD 128
#define OD 256
#define GG 256
#define NT 782              // ceil(NN/128); NT*128 = 100096

// ---------------- scratch ----------------
__device__ __half g_th[(size_t)NN * HD];                // transformed features (fp16)
__device__ __half g_hh[(size_t)NN * HD];                // final layer H (fp16)
__device__ __nv_bfloat16 g_ah[(size_t)NT * 128 * 128];  // A hi [row*128+k]
__device__ __nv_bfloat16 g_al[(size_t)NT * 128 * 128];  // A lo
__device__ __nv_bfloat16 g_bh[3 * 128 * 128];           // W^T hi per layer [n*128+k]
__device__ __nv_bfloat16 g_bl[3 * 128 * 128];           // W^T lo
__device__ int   g_src[EE];
__device__ int   g_slot[EE];                            // per-edge slot offset within target
__device__ int   g_cnt[NN];
__device__ int   g_scan[NN];
__device__ int   g_bsum[256];
__device__ float g_dinv[NN];

// ---------------- helpers ----------------
__device__ __forceinline__ uint32_t pack2_hl(float a, float b, uint32_t* lo) {
    __nv_bfloat16 ha = __float2bfloat16(a), hb = __float2bfloat16(b);
    float ra = a - __bfloat162float(ha);
    float rb = b - __bfloat162float(hb);
    *lo = (uint32_t)__bfloat16_as_ushort(__float2bfloat16(ra))
        | ((uint32_t)__bfloat16_as_ushort(__float2bfloat16(rb)) << 16);
    return (uint32_t)__bfloat16_as_ushort(ha)
         | ((uint32_t)__bfloat16_as_ushort(hb) << 16);
}

__device__ __forceinline__ unsigned long long pack_hi4(float4 v, float4* lo_out) {
    __nv_bfloat16 h0 = __float2bfloat16(v.x), h1 = __float2bfloat16(v.y);
    __nv_bfloat16 h2 = __float2bfloat16(v.z), h3 = __float2bfloat16(v.w);
    lo_out->x = v.x - __bfloat162float(h0);
    lo_out->y = v.y - __bfloat162float(h1);
    lo_out->z = v.z - __bfloat162float(h2);
    lo_out->w = v.w - __bfloat162float(h3);
    return (unsigned long long)__bfloat16_as_ushort(h0)
         | ((unsigned long long)__bfloat16_as_ushort(h1) << 16)
         | ((unsigned long long)__bfloat16_as_ushort(h2) << 32)
         | ((unsigned long long)__bfloat16_as_ushort(h3) << 48);
}
__device__ __forceinline__ unsigned long long pack_lo4(float4 v) {
    return (unsigned long long)__bfloat16_as_ushort(__float2bfloat16(v.x))
         | ((unsigned long long)__bfloat16_as_ushort(__float2bfloat16(v.y)) << 16)
         | ((unsigned long long)__bfloat16_as_ushort(__float2bfloat16(v.z)) << 32)
         | ((unsigned long long)__bfloat16_as_ushort(__float2bfloat16(v.w)) << 48);
}

__device__ __forceinline__ void mma_bf16(float* c, uint32_t a0, uint32_t a1,
                                         uint32_t a2, uint32_t a3,
                                         uint32_t b0, uint32_t b1) {
    asm volatile(
        "mma.sync.aligned.m16n8k16.row.col.f32.bf16.bf16.f32 "
        "{%0,%1,%2,%3}, {%4,%5,%6,%7}, {%8,%9}, {%0,%1,%2,%3};"
        : "+f"(c[0]), "+f"(c[1]), "+f"(c[2]), "+f"(c[3])
        : "r"(a0), "r"(a1), "r"(a2), "r"(a3), "r"(b0), "r"(b1));
}

__device__ __forceinline__ float4 unpack_h4(uint2 q) {
    __half2 h0 = *(__half2*)&q.x;
    __half2 h1 = *(__half2*)&q.y;
    float2 f0 = __half22float2(h0);
    float2 f1 = __half22float2(h1);
    return make_float4(f0.x, f0.y, f1.x, f1.y);
}

// ---------------- prep (side stream) ----------------
// edge_index is int32 (JAX x64 disabled). Atomic here doubles as slot assigner.
__global__ void k_edges(const int* __restrict__ ei, int e_total, int n) {
    int e = blockIdx.x * blockDim.x + threadIdx.x;
    if (e >= e_total) return;
    int r = ei[e];
    int c = ei[e_total + e];
    if ((unsigned)r >= (unsigned)n || (unsigned)c >= (unsigned)n) { g_slot[e] = -1; return; }
    g_slot[e] = atomicAdd(&g_cnt[c], 1);
}

#define SCAN_B 1024
__global__ void k_scan1(int n) {
    __shared__ int s[SCAN_B];
    int tid = threadIdx.x;
    int v = blockIdx.x * SCAN_B + tid;
    int c = (v < n) ? g_cnt[v] : 0;
    if (v < n) g_dinv[v] = rsqrtf((float)(c + 1));   // +1 self-loop
    s[tid] = c;
    __syncthreads();
    #pragma unroll
    for (int off = 1; off < SCAN_B; off <<= 1) {
        int t = (tid >= off) ? s[tid - off] : 0;
        __syncthreads();
        s[tid] += t;
        __syncthreads();
    }
    if (v < n) g_scan[v] = s[tid] - c;    // exclusive within block
    if (tid == SCAN_B - 1) g_bsum[blockIdx.x] = s[tid];
}

__global__ void k_scan2(int nblocks) {
    __shared__ int s[128];
    int t = threadIdx.x;
    int v = (t < nblocks) ? g_bsum[t] : 0;
    s[t] = v;
    __syncthreads();
    #pragma unroll
    for (int off = 1; off < 128; off <<= 1) {
        int u = (t >= off) ? s[t - off] : 0;
        __syncthreads();
        s[t] += u;
        __syncthreads();
    }
    if (t < nblocks) g_bsum[t] = s[t] - v;   // exclusive
}

// atomic-free CSR fill: one scattered 4B store per edge
__global__ void k_fill(const int* __restrict__ ei, int e_total, int n) {
    int e = blockIdx.x * blockDim.x + threadIdx.x;
    if (e >= e_total) return;
    int off = g_slot[e];
    if (off < 0) return;
    int r = ei[e];
    int c = ei[e_total + e];
    int base = g_scan[c] + g_bsum[c >> 10];
    g_src[base + off] = r;
}

// W^T -> bf16 hi/lo, coalesced smem-tile transpose (all 3 layers)
__global__ void k_prep_w_all(const float* __restrict__ W0,
                             const float* __restrict__ W1,
                             const float* __restrict__ W2) {
    __shared__ float tile[32][33];
    int l = blockIdx.z;
    const float* W = (l == 0) ? W0 : ((l == 1) ? W1 : W2);
    int k0 = blockIdx.y * 32;
    int n0 = blockIdx.x * 32;
    int tx = threadIdx.x, ty = threadIdx.y;
    #pragma unroll
    for (int i = 0; i < 32; i += 8)
        tile[ty + i][tx] = W[(size_t)(k0 + ty + i) * 128 + n0 + tx];
    __syncthreads();
    __nv_bfloat16* bh = g_bh + (size_t)l * 16384;
    __nv_bfloat16* bl = g_bl + (size_t)l * 16384;
    #pragma unroll
    for (int i = 0; i < 32; i += 8) {
        float w = tile[tx][ty + i];
        __nv_bfloat16 hi = __float2bfloat16(w);
        __nv_bfloat16 lo = __float2bfloat16(w - __bfloat162float(hi));
        bh[(size_t)(n0 + ty + i) * 128 + k0 + tx] = hi;
        bl[(size_t)(n0 + ty + i) * 128 + k0 + tx] = lo;
    }
}

// ---------------- HMMA GEMM: T(fp16) = A @ W ----------------
// SRC 0: A = fp32 X (split in-register); SRC 1: A = g_ah/g_al bf16 pair
#define BPAD 72
template<int SRC>
__global__ __launch_bounds__(256) void k_gemm_t(const float* __restrict__ X,
                                                const __nv_bfloat16* __restrict__ Ah,
                                                const __nv_bfloat16* __restrict__ Al,
                                                const __nv_bfloat16* __restrict__ Bh,
                                                const __nv_bfloat16* __restrict__ Bl,
                                                __half* __restrict__ Th, int n) {
    __shared__ __align__(16) __nv_bfloat16 sBh[128][BPAD];
    __shared__ __align__(16) __nv_bfloat16 sBl[128][BPAD];

    int tid = threadIdx.x;
    int wid = tid >> 5;
    int lane = tid & 31;
    int g = lane >> 2;
    int t = lane & 3;
    int row_base = blockIdx.x * 128 + wid * 16;
    int r0 = row_base + g;

    float acc[16][4];
    #pragma unroll
    for (int nt = 0; nt < 16; nt++)
        #pragma unroll
        for (int j = 0; j < 4; j++) acc[nt][j] = 0.0f;

    #pragma unroll 1
    for (int kh = 0; kh < 2; kh++) {
        {
            const uint4* srcH = (const uint4*)(Bh + kh * 64);
            const uint4* srcL = (const uint4*)(Bl + kh * 64);
            #pragma unroll
            for (int i = tid; i < 128 * 8; i += 256) {
                int nrow = i >> 3, q = i & 7;
                *(uint4*)&sBh[nrow][q * 8] = srcH[nrow * 16 + q];
                *(uint4*)&sBl[nrow][q * 8] = srcL[nrow * 16 + q];
            }
        }
        __syncthreads();

        #pragma unroll
        for (int kc = 0; kc < 4; kc++) {
            int kabs = kh * 64 + kc * 16;
            uint32_t ah0, ah1, ah2, ah3, al0, al1, al2, al3;
            if (SRC == 0) {
                int rA = (r0 < n) ? r0 : (n - 1);
                int rB = (r0 + 8 < n) ? (r0 + 8) : (n - 1);
                const float* px0 = X + (size_t)rA * 128 + kabs + t * 2;
                const float* px1 = X + (size_t)rB * 128 + kabs + t * 2;
                float2 f0 = *(const float2*)px0;
                float2 f1 = *(const float2*)px1;
                float2 f2 = *(const float2*)(px0 + 8);
                float2 f3 = *(const float2*)(px1 + 8);
                ah0 = pack2_hl(f0.x, f0.y, &al0);
                ah1 = pack2_hl(f1.x, f1.y, &al1);
                ah2 = pack2_hl(f2.x, f2.y, &al2);
                ah3 = pack2_hl(f3.x, f3.y, &al3);
            } else {
                const __nv_bfloat16* pa0 = Ah + (size_t)r0 * 128 + kabs + t * 2;
                const __nv_bfloat16* pa1 = pa0 + 8 * 128;
                const __nv_bfloat16* pl0 = Al + (size_t)r0 * 128 + kabs + t * 2;
                const __nv_bfloat16* pl1 = pl0 + 8 * 128;
                ah0 = *(const uint32_t*)pa0;
                ah1 = *(const uint32_t*)pa1;
                ah2 = *(const uint32_t*)(pa0 + 8);
                ah3 = *(const uint32_t*)(pa1 + 8);
                al0 = *(const uint32_t*)pl0;
                al1 = *(const uint32_t*)pl1;
                al2 = *(const uint32_t*)(pl0 + 8);
                al3 = *(const uint32_t*)(pl1 + 8);
            }

            int ks = kc * 16 + t * 2;
            #pragma unroll
            for (int nt = 0; nt < 16; nt++) {
                int nrow = nt * 8 + g;
                uint32_t bh0 = *(const uint32_t*)&sBh[nrow][ks];
                uint32_t bh1 = *(const uint32_t*)&sBh[nrow][ks + 8];
                uint32_t bl0 = *(const uint32_t*)&sBl[nrow][ks];
                uint32_t bl1 = *(const uint32_t*)&sBl[nrow][ks + 8];
                mma_bf16(acc[nt], ah0, ah1, ah2, ah3, bh0, bh1);
                mma_bf16(acc[nt], ah0, ah1, ah2, ah3, bl0, bl1);
                mma_bf16(acc[nt], al0, al1, al2, al3, bh0, bh1);
            }
        }
        __syncthreads();
    }

    bool w0 = (r0 < n), w1 = (r0 + 8 < n);
    #pragma unroll
    for (int nt = 0; nt < 16; nt++) {
        int col = nt * 8 + t * 2;
        if (w0) *(__half2*)(Th + (size_t)r0 * 128 + col)
                    = __floats2half2_rn(acc[nt][0], acc[nt][1]);
        if (w1) *(__half2*)(Th + (size_t)(r0 + 8) * 128 + col)
                    = __floats2half2_rn(acc[nt][2], acc[nt][3]);
    }
}

// ---------------- aggregate (fp16 gather, weights recomputed) ----------------
// MODE 0: write bf16 hi/lo (feeds next GEMM); MODE 1: write fp16 H (feeds pool)
template<int MODE>
__global__ __launch_bounds__(256) void k_agg_t(const __half* __restrict__ Th,
                                               const float* __restrict__ bias, int n) {
    int warp = (blockIdx.x * blockDim.x + threadIdx.x) >> 5;
    int lane = threadIdx.x & 31;
    if (warp >= n) return;
    int v = warp;
    const uint2* T2 = (const uint2*)Th;
    float dv = g_dinv[v];
    float s = dv * dv;
    float4 self = unpack_h4(T2[(size_t)v * 32 + lane]);
    float4 acc = make_float4(self.x * s, self.y * s, self.z * s, self.w * s);

    int start = g_scan[v] + g_bsum[v >> 10];
    int cnt = g_cnt[v];
    int i = 0;
    for (; i + 4 <= cnt; i += 4) {
        int s0 = g_src[start + i],     s1 = g_src[start + i + 1];
        int s2 = g_src[start + i + 2], s3 = g_src[start + i + 3];
        float w0 = dv * g_dinv[s0], w1 = dv * g_dinv[s1];
        float w2 = dv * g_dinv[s2], w3 = dv * g_dinv[s3];
        uint2 q0 = T2[(size_t)s0 * 32 + lane];
        uint2 q1 = T2[(size_t)s1 * 32 + lane];
        uint2 q2 = T2[(size_t)s2 * 32 + lane];
        uint2 q3 = T2[(size_t)s3 * 32 + lane];
        float4 x0 = unpack_h4(q0), x1 = unpack_h4(q1);
        float4 x2 = unpack_h4(q2), x3 = unpack_h4(q3);
        acc.x += w0 * x0.x + w1 * x1.x + w2 * x2.x + w3 * x3.x;
        acc.y += w0 * x0.y + w1 * x1.y + w2 * x2.y + w3 * x3.y;
        acc.z += w0 * x0.z + w1 * x1.z + w2 * x2.z + w3 * x3.z;
        acc.w += w0 * x0.w + w1 * x1.w + w2 * x2.w + w3 * x3.w;
    }
    for (; i < cnt; i++) {
        int s0 = g_src[start + i];
        float w0 = dv * g_dinv[s0];
        float4 x0 = unpack_h4(T2[(size_t)s0 * 32 + lane]);
        acc.x += w0 * x0.x; acc.y += w0 * x0.y; acc.z += w0 * x0.z; acc.w += w0 * x0.w;
    }
    float4 b = ((const float4*)bias)[lane];
    acc.x = fmaxf(acc.x + b.x, 0.f);
    acc.y = fmaxf(acc.y + b.y, 0.f);
    acc.z = fmaxf(acc.z + b.z, 0.f);
    acc.w = fmaxf(acc.w + b.w, 0.f);

    if (MODE == 1) {
        uint2 q;
        *(__half2*)&q.x = __floats2half2_rn(acc.x, acc.y);
        *(__half2*)&q.y = __floats2half2_rn(acc.z, acc.w);
        ((uint2*)g_hh)[(size_t)v * 32 + lane] = q;
    } else {
        float4 lo4;
        unsigned long long hp = pack_hi4(acc, &lo4);
        unsigned long long lp = pack_lo4(lo4);
        size_t off = (size_t)v * 128 + lane * 4;
        *(unsigned long long*)(g_ah + off) = hp;
        *(unsigned long long*)(g_al + off) = lp;
    }
}

// ---------------- fused pool + fc ----------------
__device__ __forceinline__ int lb_i(const int* a, int n, int key) {
    int lo = 0, hi = n;
    while (lo < hi) { int mid = (lo + hi) >> 1; if (a[mid] < key) lo = mid + 1; else hi = mid; }
    return lo;
}

__global__ __launch_bounds__(256) void k_poolfc(const int* __restrict__ batch,
                                                const float* __restrict__ Wfc,
                                                const float* __restrict__ bfc,
                                                float* __restrict__ out, int n) {
    int g = blockIdx.x;
    int tid = threadIdx.x;
    __shared__ int s_lo, s_hi;
    __shared__ float part[2][128];
    __shared__ float p[128];
    if (tid == 0) s_lo = lb_i(batch, n, g);
    if (tid == 1) s_hi = lb_i(batch, n, g + 1);
    __syncthreads();
    int lo = s_lo, hi = s_hi;
    int k = tid & 127;
    int half = tid >> 7;
    int mid = (lo + hi) >> 1;
    int a = half ? mid : lo;
    int b = half ? hi : mid;
    float acc = 0.f;
    for (int v = a; v < b; v++) acc += __half2float(g_hh[(size_t)v * 128 + k]);
    part[half][k] = acc;
    __syncthreads();
    if (tid < 128)
        p[tid] = (part[0][tid] + part[1][tid]) / fmaxf((float)(hi - lo), 1.0f);
    __syncthreads();
    int o = tid;
    float oacc = bfc[o];
    #pragma unroll 8
    for (int kk = 0; kk < 128; kk++) oacc += p[kk] * Wfc[(size_t)kk * 256 + o];
    out[(size_t)g * 256 + o] = oacc;
}

// ---------------- launch ----------------
extern "C" void kernel_launch(void* const* d_in, const int* in_sizes, int n_in,
                              void* d_out, int out_size) {
    const float *x = 0, *Wfc = 0, *bfc = 0;
    const float *Wl[3] = {0, 0, 0};
    const float *bl[3] = {0, 0, 0};
    const int *ei = 0, *batch = 0;
    int nW = 0, nb = 0;
    for (int i = 0; i < n_in; i++) {
        int s = in_sizes[i];
        const void* p = d_in[i];
        if (s == NN * FD)            x = (const float*)p;
        else if (s == FD * HD) {     if (nW < 3) Wl[nW++] = (const float*)p; }
        else if (s == HD)        {   if (nb < 3) bl[nb++] = (const float*)p; }
        else if (s == HD * OD)       Wfc = (const float*)p;
        else if (s == OD)            bfc = (const float*)p;
        else if (s == 2 * EE)        ei = (const int*)p;
        else if (s == NN)            batch = (const int*)p;
    }
    float* out = (float*)d_out;

    int n = NN, e = EE;

    // lazy host-side resources (no device allocations)
    static cudaStream_t s1 = 0;
    static cudaEvent_t evFork = 0, evJoin = 0;
    if (!s1) {
        cudaStreamCreateWithFlags(&s1, cudaStreamNonBlocking);
        cudaEventCreateWithFlags(&evFork, cudaEventDisableTiming);
        cudaEventCreateWithFlags(&evJoin, cudaEventDisableTiming);
    }

    __half* th_ptr;
    cudaGetSymbolAddress((void**)&th_ptr, g_th);
    __nv_bfloat16 *ah_ptr, *al_ptr, *bh_ptr, *bl_ptr;
    cudaGetSymbolAddress((void**)&ah_ptr, g_ah);
    cudaGetSymbolAddress((void**)&al_ptr, g_al);
    cudaGetSymbolAddress((void**)&bh_ptr, g_bh);
    cudaGetSymbolAddress((void**)&bl_ptr, g_bl);
    int* cnt_ptr;
    cudaGetSymbolAddress((void**)&cnt_ptr, g_cnt);

    int nb_e = (e + 255) / 256;
    int nb_scan = (n + SCAN_B - 1) / SCAN_B;
    int nb_warp = (n * 32 + 255) / 256;

    // ---- fork: CSR prep on side stream s1 ----
    cudaEventRecord(evFork, 0);
    cudaStreamWaitEvent(s1, evFork, 0);
    cudaMemsetAsync(cnt_ptr, 0, (size_t)n * sizeof(int), s1);
    k_edges<<<nb_e, 256, 0, s1>>>(ei, e, n);
    k_scan1<<<nb_scan, SCAN_B, 0, s1>>>(n);
    k_scan2<<<1, 128, 0, s1>>>(nb_scan);
    k_fill<<<nb_e, 256, 0, s1>>>(ei, e, n);
    cudaEventRecord(evJoin, s1);

    // ---- main stream: weights + GEMM1 (reads fp32 x directly) ----
    k_prep_w_all<<<dim3(4, 4, 3), dim3(32, 8)>>>(Wl[0], Wl[1], Wl[2]);
    k_gemm_t<0><<<NT, 256>>>(x, ah_ptr, al_ptr, bh_ptr, bl_ptr, th_ptr, n);

    // ---- join ----
    cudaStreamWaitEvent(0, evJoin, 0);

    // layer 1 agg, then layers 2/3
    k_agg_t<0><<<nb_warp, 256>>>(th_ptr, bl[0], n);
    k_gemm_t<1><<<NT, 256>>>(x, ah_ptr, al_ptr, bh_ptr + 16384, bl_ptr + 16384, th_ptr, n);
    k_agg_t<0><<<nb_warp, 256>>>(th_ptr, bl[1], n);
    k_gemm_t<1><<<NT, 256>>>(x, ah_ptr, al_ptr, bh_ptr + 32768, bl_ptr + 32768, th_ptr, n);
    k_agg_t<1><<<nb_warp, 256>>>(th_ptr, bl[2], n);

    // fused pool + fc
    k_poolfc<<<GG, 256>>>(batch, Wfc, bfc, out, n);
}

// round 17
// speedup vs baseline: 1.7373x; 1.1066x over previous
#include <cuda_runtime.h>
#include <cuda_bf16.h>
#include <cuda_fp16.h>
#include <math.h>
#include <stdint.h>

// Problem constants
#define NN 100000
#define EE 1600000
#define FD 128
#define HD 128
#define OD 256
#define GG 256
#define NT 782              // ceil(NN/128); NT*128 = 100096

// ---------------- scratch ----------------
__device__ __half g_th[(size_t)NN * HD];   // GEMM output T (fp16)
__device__ __half g_hh[(size_t)NN * HD];   // agg output H (fp16) - every layer
__device__ __nv_bfloat16 g_bh[3 * 128 * 128];  // W^T hi per layer [n*128+k]
__device__ __nv_bfloat16 g_bl[3 * 128 * 128];  // W^T lo
__device__ int   g_src[EE];
__device__ int   g_slot[EE];               // per-edge slot offset within target
__device__ int   g_cnt[NN];
__device__ int   g_scan[NN];
__device__ int   g_bsum[256];
__device__ float g_dinv[NN];

// ---------------- helpers ----------------
__device__ __forceinline__ uint32_t pack2_hl(float a, float b, uint32_t* lo) {
    __nv_bfloat16 ha = __float2bfloat16(a), hb = __float2bfloat16(b);
    float ra = a - __bfloat162float(ha);
    float rb = b - __bfloat162float(hb);
    *lo = (uint32_t)__bfloat16_as_ushort(__float2bfloat16(ra))
        | ((uint32_t)__bfloat16_as_ushort(__float2bfloat16(rb)) << 16);
    return (uint32_t)__bfloat16_as_ushort(ha)
         | ((uint32_t)__bfloat16_as_ushort(hb) << 16);
}

__device__ __forceinline__ void mma_bf16(float* c, uint32_t a0, uint32_t a1,
                                         uint32_t a2, uint32_t a3,
                                         uint32_t b0, uint32_t b1) {
    asm volatile(
        "mma.sync.aligned.m16n8k16.row.col.f32.bf16.bf16.f32 "
        "{%0,%1,%2,%3}, {%4,%5,%6,%7}, {%8,%9}, {%0,%1,%2,%3};"
        : "+f"(c[0]), "+f"(c[1]), "+f"(c[2]), "+f"(c[3])
        : "r"(a0), "r"(a1), "r"(a2), "r"(a3), "r"(b0), "r"(b1));
}

__device__ __forceinline__ float4 unpack_h4(uint2 q) {
    __half2 h0 = *(__half2*)&q.x;
    __half2 h1 = *(__half2*)&q.y;
    float2 f0 = __half22float2(h0);
    float2 f1 = __half22float2(h1);
    return make_float4(f0.x, f0.y, f1.x, f1.y);
}

// ---------------- prep (side stream) ----------------
// 4 edges per thread via int4 loads. Atomic doubles as slot assigner.
__global__ void k_edges(const int* __restrict__ ei, int e_total, int n) {
    int e0 = (blockIdx.x * blockDim.x + threadIdx.x) * 4;
    if (e0 >= e_total) return;
    if (e0 + 4 <= e_total) {
        int4 rr = *(const int4*)(ei + e0);
        int4 cc = *(const int4*)(ei + e_total + e0);
        int4 sl;
        sl.x = ((unsigned)rr.x < (unsigned)n && (unsigned)cc.x < (unsigned)n) ? atomicAdd(&g_cnt[cc.x], 1) : -1;
        sl.y = ((unsigned)rr.y < (unsigned)n && (unsigned)cc.y < (unsigned)n) ? atomicAdd(&g_cnt[cc.y], 1) : -1;
        sl.z = ((unsigned)rr.z < (unsigned)n && (unsigned)cc.z < (unsigned)n) ? atomicAdd(&g_cnt[cc.z], 1) : -1;
        sl.w = ((unsigned)rr.w < (unsigned)n && (unsigned)cc.w < (unsigned)n) ? atomicAdd(&g_cnt[cc.w], 1) : -1;
        *(int4*)(g_slot + e0) = sl;
    } else {
        for (int e = e0; e < e_total; e++) {
            int r = ei[e], c = ei[e_total + e];
            g_slot[e] = ((unsigned)r < (unsigned)n && (unsigned)c < (unsigned)n)
                      ? atomicAdd(&g_cnt[c], 1) : -1;
        }
    }
}

#define SCAN_B 1024
__global__ void k_scan1(int n) {
    __shared__ int s[SCAN_B];
    int tid = threadIdx.x;
    int v = blockIdx.x * SCAN_B + tid;
    int c = (v < n) ? g_cnt[v] : 0;
    if (v < n) g_dinv[v] = rsqrtf((float)(c + 1));   // +1 self-loop
    s[tid] = c;
    __syncthreads();
    #pragma unroll
    for (int off = 1; off < SCAN_B; off <<= 1) {
        int t = (tid >= off) ? s[tid - off] : 0;
        __syncthreads();
        s[tid] += t;
        __syncthreads();
    }
    if (v < n) g_scan[v] = s[tid] - c;    // exclusive within block
    if (tid == SCAN_B - 1) g_bsum[blockIdx.x] = s[tid];
}

__global__ void k_scan2(int nblocks) {
    __shared__ int s[128];
    int t = threadIdx.x;
    int v = (t < nblocks) ? g_bsum[t] : 0;
    s[t] = v;
    __syncthreads();
    #pragma unroll
    for (int off = 1; off < 128; off <<= 1) {
        int u = (t >= off) ? s[t - off] : 0;
        __syncthreads();
        s[t] += u;
        __syncthreads();
    }
    if (t < nblocks) g_bsum[t] = s[t] - v;   // exclusive
}

// atomic-free CSR fill: one scattered 4B store per valid edge, 4 edges/thread
__global__ void k_fill(const int* __restrict__ ei, int e_total, int n) {
    int e0 = (blockIdx.x * blockDim.x + threadIdx.x) * 4;
    if (e0 >= e_total) return;
    int lim = (e0 + 4 <= e_total) ? 4 : (e_total - e0);
    int4 sl4 = {0,0,0,0};
    int4 rr4 = {0,0,0,0};
    int4 cc4 = {0,0,0,0};
    if (lim == 4) {
        sl4 = *(const int4*)(g_slot + e0);
        rr4 = *(const int4*)(ei + e0);
        cc4 = *(const int4*)(ei + e_total + e0);
    } else {
        int* s = (int*)&sl4; int* r = (int*)&rr4; int* c = (int*)&cc4;
        for (int j = 0; j < lim; j++) { s[j] = g_slot[e0+j]; r[j] = ei[e0+j]; c[j] = ei[e_total+e0+j]; }
    }
    const int* s = (const int*)&sl4;
    const int* r = (const int*)&rr4;
    const int* c = (const int*)&cc4;
    #pragma unroll
    for (int j = 0; j < 4; j++) {
        if (j < lim && s[j] >= 0) {
            int base = g_scan[c[j]] + g_bsum[c[j] >> 10];
            g_src[base + s[j]] = r[j];
        }
    }
}

// W^T -> bf16 hi/lo, coalesced smem-tile transpose (all 3 layers)
__global__ void k_prep_w_all(const float* __restrict__ W0,
                             const float* __restrict__ W1,
                             const float* __restrict__ W2) {
    __shared__ float tile[32][33];
    int l = blockIdx.z;
    const float* W = (l == 0) ? W0 : ((l == 1) ? W1 : W2);
    int k0 = blockIdx.y * 32;
    int n0 = blockIdx.x * 32;
    int tx = threadIdx.x, ty = threadIdx.y;
    #pragma unroll
    for (int i = 0; i < 32; i += 8)
        tile[ty + i][tx] = W[(size_t)(k0 + ty + i) * 128 + n0 + tx];
    __syncthreads();
    __nv_bfloat16* bh = g_bh + (size_t)l * 16384;
    __nv_bfloat16* bl = g_bl + (size_t)l * 16384;
    #pragma unroll
    for (int i = 0; i < 32; i += 8) {
        float w = tile[tx][ty + i];
        __nv_bfloat16 hi = __float2bfloat16(w);
        __nv_bfloat16 lo = __float2bfloat16(w - __bfloat162float(hi));
        bh[(size_t)(n0 + ty + i) * 128 + k0 + tx] = hi;
        bl[(size_t)(n0 + ty + i) * 128 + k0 + tx] = lo;
    }
}

// ---------------- HMMA GEMM: T(fp16) = A @ W ----------------
// SRC 0: A = fp32 X; SRC 2: A = fp16 H (exact bf16 hi/lo split in-register)
#define BPAD 72
template<int SRC>
__global__ __launch_bounds__(256) void k_gemm_t(const float* __restrict__ X,
                                                const __half* __restrict__ Hh,
                                                const __nv_bfloat16* __restrict__ Bh,
                                                const __nv_bfloat16* __restrict__ Bl,
                                                __half* __restrict__ Th, int n) {
    __shared__ __align__(16) __nv_bfloat16 sBh[128][BPAD];
    __shared__ __align__(16) __nv_bfloat16 sBl[128][BPAD];

    int tid = threadIdx.x;
    int wid = tid >> 5;
    int lane = tid & 31;
    int g = lane >> 2;
    int t = lane & 3;
    int row_base = blockIdx.x * 128 + wid * 16;
    int r0 = row_base + g;

    float acc[16][4];
    #pragma unroll
    for (int nt = 0; nt < 16; nt++)
        #pragma unroll
        for (int j = 0; j < 4; j++) acc[nt][j] = 0.0f;

    #pragma unroll 1
    for (int kh = 0; kh < 2; kh++) {
        {
            const uint4* srcH = (const uint4*)(Bh + kh * 64);
            const uint4* srcL = (const uint4*)(Bl + kh * 64);
            #pragma unroll
            for (int i = tid; i < 128 * 8; i += 256) {
                int nrow = i >> 3, q = i & 7;
                *(uint4*)&sBh[nrow][q * 8] = srcH[nrow * 16 + q];
                *(uint4*)&sBl[nrow][q * 8] = srcL[nrow * 16 + q];
            }
        }
        __syncthreads();

        #pragma unroll
        for (int kc = 0; kc < 4; kc++) {
            int kabs = kh * 64 + kc * 16;
            uint32_t ah0, ah1, ah2, ah3, al0, al1, al2, al3;
            int rA = (r0 < n) ? r0 : (n - 1);
            int rB = (r0 + 8 < n) ? (r0 + 8) : (n - 1);
            if (SRC == 0) {
                const float* px0 = X + (size_t)rA * 128 + kabs + t * 2;
                const float* px1 = X + (size_t)rB * 128 + kabs + t * 2;
                float2 f0 = *(const float2*)px0;
                float2 f1 = *(const float2*)px1;
                float2 f2 = *(const float2*)(px0 + 8);
                float2 f3 = *(const float2*)(px1 + 8);
                ah0 = pack2_hl(f0.x, f0.y, &al0);
                ah1 = pack2_hl(f1.x, f1.y, &al1);
                ah2 = pack2_hl(f2.x, f2.y, &al2);
                ah3 = pack2_hl(f3.x, f3.y, &al3);
            } else {
                const __half* ph0 = Hh + (size_t)rA * 128 + kabs + t * 2;
                const __half* ph1 = Hh + (size_t)rB * 128 + kabs + t * 2;
                float2 f0 = __half22float2(*(const __half2*)ph0);
                float2 f1 = __half22float2(*(const __half2*)ph1);
                float2 f2 = __half22float2(*(const __half2*)(ph0 + 8));
                float2 f3 = __half22float2(*(const __half2*)(ph1 + 8));
                ah0 = pack2_hl(f0.x, f0.y, &al0);
                ah1 = pack2_hl(f1.x, f1.y, &al1);
                ah2 = pack2_hl(f2.x, f2.y, &al2);
                ah3 = pack2_hl(f3.x, f3.y, &al3);
            }

            int ks = kc * 16 + t * 2;
            #pragma unroll
            for (int nt = 0; nt < 16; nt++) {
                int nrow = nt * 8 + g;
                uint32_t bh0 = *(const uint32_t*)&sBh[nrow][ks];
                uint32_t bh1 = *(const uint32_t*)&sBh[nrow][ks + 8];
                uint32_t bl0 = *(const uint32_t*)&sBl[nrow][ks];
                uint32_t bl1 = *(const uint32_t*)&sBl[nrow][ks + 8];
                mma_bf16(acc[nt], ah0, ah1, ah2, ah3, bh0, bh1);
                mma_bf16(acc[nt], ah0, ah1, ah2, ah3, bl0, bl1);
                mma_bf16(acc[nt], al0, al1, al2, al3, bh0, bh1);
            }
        }
        __syncthreads();
    }

    bool w0 = (r0 < n), w1 = (r0 + 8 < n);
    #pragma unroll
    for (int nt = 0; nt < 16; nt++) {
        int col = nt * 8 + t * 2;
        if (w0) *(__half2*)(Th + (size_t)r0 * 128 + col)
                    = __floats2half2_rn(acc[nt][0], acc[nt][1]);
        if (w1) *(__half2*)(Th + (size_t)(r0 + 8) * 128 + col)
                    = __floats2half2_rn(acc[nt][2], acc[nt][3]);
    }
}

// ---------------- aggregate (fp16 gather, fp16 out, 8-way ILP) ----------------
__global__ __launch_bounds__(256) void k_agg(const __half* __restrict__ Th,
                                             const float* __restrict__ bias, int n) {
    int warp = (blockIdx.x * blockDim.x + threadIdx.x) >> 5;
    int lane = threadIdx.x & 31;
    if (warp >= n) return;
    int v = warp;
    const uint2* T2 = (const uint2*)Th;
    float dv = g_dinv[v];
    float s = dv * dv;
    float4 self = unpack_h4(T2[(size_t)v * 32 + lane]);
    float4 acc = make_float4(self.x * s, self.y * s, self.z * s, self.w * s);

    int start = g_scan[v] + g_bsum[v >> 10];
    int cnt = g_cnt[v];
    int i = 0;
    for (; i + 8 <= cnt; i += 8) {
        int   sv[8]; float wv[8]; uint2 qv[8];
        #pragma unroll
        for (int j = 0; j < 8; j++) sv[j] = g_src[start + i + j];
        #pragma unroll
        for (int j = 0; j < 8; j++) qv[j] = T2[(size_t)sv[j] * 32 + lane];
        #pragma unroll
        for (int j = 0; j < 8; j++) wv[j] = dv * g_dinv[sv[j]];
        #pragma unroll
        for (int j = 0; j < 8; j++) {
            float4 x = unpack_h4(qv[j]);
            acc.x += wv[j] * x.x; acc.y += wv[j] * x.y;
            acc.z += wv[j] * x.z; acc.w += wv[j] * x.w;
        }
    }
    for (; i < cnt; i++) {
        int s0 = g_src[start + i];
        float w0 = dv * g_dinv[s0];
        float4 x0 = unpack_h4(T2[(size_t)s0 * 32 + lane]);
        acc.x += w0 * x0.x; acc.y += w0 * x0.y; acc.z += w0 * x0.z; acc.w += w0 * x0.w;
    }
    float4 b = ((const float4*)bias)[lane];
    acc.x = fmaxf(acc.x + b.x, 0.f);
    acc.y = fmaxf(acc.y + b.y, 0.f);
    acc.z = fmaxf(acc.z + b.z, 0.f);
    acc.w = fmaxf(acc.w + b.w, 0.f);

    uint2 q;
    *(__half2*)&q.x = __floats2half2_rn(acc.x, acc.y);
    *(__half2*)&q.y = __floats2half2_rn(acc.z, acc.w);
    ((uint2*)g_hh)[(size_t)v * 32 + lane] = q;
}

// ---------------- fused pool + fc ----------------
__device__ __forceinline__ int lb_i(const int* a, int n, int key) {
    int lo = 0, hi = n;
    while (lo < hi) { int mid = (lo + hi) >> 1; if (a[mid] < key) lo = mid + 1; else hi = mid; }
    return lo;
}

__global__ __launch_bounds__(256) void k_poolfc(const int* __restrict__ batch,
                                                const float* __restrict__ Wfc,
                                                const float* __restrict__ bfc,
                                                float* __restrict__ out, int n) {
    int g = blockIdx.x;
    int tid = threadIdx.x;
    __shared__ int s_lo, s_hi;
    __shared__ float part[2][128];
    __shared__ float p[128];
    if (tid == 0) s_lo = lb_i(batch, n, g);
    if (tid == 1) s_hi = lb_i(batch, n, g + 1);
    __syncthreads();
    int lo = s_lo, hi = s_hi;
    int k = tid & 127;
    int half = tid >> 7;
    int mid = (lo + hi) >> 1;
    int a = half ? mid : lo;
    int b = half ? hi : mid;
    float acc = 0.f;
    for (int v = a; v < b; v++) acc += __half2float(g_hh[(size_t)v * 128 + k]);
    part[half][k] = acc;
    __syncthreads();
    if (tid < 128)
        p[tid] = (part[0][tid] + part[1][tid]) / fmaxf((float)(hi - lo), 1.0f);
    __syncthreads();
    int o = tid;
    float oacc = bfc[o];
    #pragma unroll 8
    for (int kk = 0; kk < 128; kk++) oacc += p[kk] * Wfc[(size_t)kk * 256 + o];
    out[(size_t)g * 256 + o] = oacc;
}

// ---------------- launch ----------------
extern "C" void kernel_launch(void* const* d_in, const int* in_sizes, int n_in,
                              void* d_out, int out_size) {
    const float *x = 0, *Wfc = 0, *bfc = 0;
    const float *Wl[3] = {0, 0, 0};
    const float *bl[3] = {0, 0, 0};
    const int *ei = 0, *batch = 0;
    int nW = 0, nb = 0;
    for (int i = 0; i < n_in; i++) {
        int s = in_sizes[i];
        const void* p = d_in[i];
        if (s == NN * FD)            x = (const float*)p;
        else if (s == FD * HD) {     if (nW < 3) Wl[nW++] = (const float*)p; }
        else if (s == HD)        {   if (nb < 3) bl[nb++] = (const float*)p; }
        else if (s == HD * OD)       Wfc = (const float*)p;
        else if (s == OD)            bfc = (const float*)p;
        else if (s == 2 * EE)        ei = (const int*)p;
        else if (s == NN)            batch = (const int*)p;
    }
    float* out = (float*)d_out;

    int n = NN, e = EE;

    // lazy host-side resources (no device allocations)
    static cudaStream_t s1 = 0;
    static cudaEvent_t evFork = 0, evJoin = 0;
    if (!s1) {
        cudaStreamCreateWithFlags(&s1, cudaStreamNonBlocking);
        cudaEventCreateWithFlags(&evFork, cudaEventDisableTiming);
        cudaEventCreateWithFlags(&evJoin, cudaEventDisableTiming);
    }

    __half *th_ptr, *hh_ptr;
    cudaGetSymbolAddress((void**)&th_ptr, g_th);
    cudaGetSymbolAddress((void**)&hh_ptr, g_hh);
    __nv_bfloat16 *bh_ptr, *bl_ptr;
    cudaGetSymbolAddress((void**)&bh_ptr, g_bh);
    cudaGetSymbolAddress((void**)&bl_ptr, g_bl);
    int* cnt_ptr;
    cudaGetSymbolAddress((void**)&cnt_ptr, g_cnt);

    int nb_e4 = (e / 4 + 255) / 256;
    int nb_scan = (n + SCAN_B - 1) / SCAN_B;
    int nb_warp = (n * 32 + 255) / 256;

    // ---- fork: CSR prep on side stream s1 ----
    cudaEventRecord(evFork, 0);
    cudaStreamWaitEvent(s1, evFork, 0);
    cudaMemsetAsync(cnt_ptr, 0, (size_t)n * sizeof(int), s1);
    k_edges<<<nb_e4, 256, 0, s1>>>(ei, e, n);
    k_scan1<<<nb_scan, SCAN_B, 0, s1>>>(n);
    k_scan2<<<1, 128, 0, s1>>>(nb_scan);
    k_fill<<<nb_e4, 256, 0, s1>>>(ei, e, n);
    cudaEventRecord(evJoin, s1);

    // ---- main stream: weights + GEMM1 (reads fp32 x directly) ----
    k_prep_w_all<<<dim3(4, 4, 3), dim3(32, 8)>>>(Wl[0], Wl[1], Wl[2]);
    k_gemm_t<0><<<NT, 256>>>(x, hh_ptr, bh_ptr, bl_ptr, th_ptr, n);

    // ---- join ----
    cudaStreamWaitEvent(0, evJoin, 0);

    // layers
    k_agg<<<nb_warp, 256>>>(th_ptr, bl[0], n);
    k_gemm_t<2><<<NT, 256>>>(x, hh_ptr, bh_ptr + 16384, bl_ptr + 16384, th_ptr, n);
    k_agg<<<nb_warp, 256>>>(th_ptr, bl[1], n);
    k_gemm_t<2><<<NT, 256>>>(x, hh_ptr, bh_ptr + 32768, bl_ptr + 32768, th_ptr, n);
    k_agg<<<nb_warp, 256>>>(th_ptr, bl[2], n);

    // fused pool + fc
    k_poolfc<<<GG, 256>>>(batch, Wfc, bfc, out, n);
}